// round 4
// baseline (speedup 1.0000x reference)
#include <cuda_runtime.h>
#include <math.h>
#include <stdint.h>

// Problem constants
static constexpr int  BD = 4;
static constexpr int  TD = 4096;
static constexpr int  DM = 1024;           // d_model
static constexpr int  DI = 2048;           // d_inner
static constexpr size_t MROWS = (size_t)BD * TD;   // 16384

// Scratch (static __device__ arrays; allocation APIs are forbidden)
__device__ float g_xn[MROWS * DM];         //  64 MB  layernorm output
__device__ float g_xz[MROWS * 2 * DI];     // 268 MB  in-proj output (xi | z)
__device__ float g_y [MROWS * DI];         // 134 MB  gated activations
__device__ float g_wbar[DI];               // mean of C-rows of xproj_w

// ---------------------------------------------------------------------------
// wbar[c] = (1/16) * sum_{s=0..15} xproj_w[17+s, c]
// ---------------------------------------------------------------------------
__global__ void compute_wbar_k(const float* __restrict__ xproj_w)
{
    int c = blockIdx.x * blockDim.x + threadIdx.x;
    if (c < DI) {
        float s = 0.f;
        #pragma unroll
        for (int k = 0; k < 16; k++)
            s += xproj_w[(size_t)(17 + k) * DI + c];
        g_wbar[c] = s * (1.f / 16.f);
    }
}

// ---------------------------------------------------------------------------
// LayerNorm: one block per row (1024 elems), 256 threads, float4 per thread
// ---------------------------------------------------------------------------
__global__ void layernorm_k(const float* __restrict__ x,
                            const float* __restrict__ w,
                            const float* __restrict__ b)
{
    __shared__ float2 red[256];
    size_t row = blockIdx.x;
    int tid = threadIdx.x;

    const float4* xr = (const float4*)(x + row * DM);
    float4 v = xr[tid];

    float s  = v.x + v.y + v.z + v.w;
    float ss = v.x * v.x + v.y * v.y + v.z * v.z + v.w * v.w;
    red[tid] = make_float2(s, ss);
    __syncthreads();
    #pragma unroll
    for (int off = 128; off >= 1; off >>= 1) {
        if (tid < off) {
            red[tid].x += red[tid + off].x;
            red[tid].y += red[tid + off].y;
        }
        __syncthreads();
    }
    float mu  = red[0].x * (1.f / DM);
    float var = red[0].y * (1.f / DM) - mu * mu;
    float rstd = rsqrtf(var + 1e-5f);

    int c = tid * 4;
    const float4 wv = *(const float4*)(w + c);
    const float4 bv = *(const float4*)(b + c);
    float4 o;
    o.x = (v.x - mu) * rstd * wv.x + bv.x;
    o.y = (v.y - mu) * rstd * wv.y + bv.y;
    o.z = (v.z - mu) * rstd * wv.z + bv.z;
    o.w = (v.w - mu) * rstd * wv.w + bv.w;
    ((float4*)(g_xn + row * DM))[tid] = o;
}

// ---------------------------------------------------------------------------
// SGEMM (TN): C[m,n] = sum_k A[m,k] * W[n,k] + bias[n] (+ resid[m,n])
// 128x128x16 tile, 256 threads, 8x8 per thread. All dims divide the tiles.
// ---------------------------------------------------------------------------
#define BM 128
#define BN 128
#define BKK 16

__global__ __launch_bounds__(256, 2)
void sgemm_tn(const float* __restrict__ A,     // [M,K]
              const float* __restrict__ W,     // [N,K]
              const float* __restrict__ bias,  // [N]
              const float* __restrict__ resid, // [M,N] or nullptr
              float* __restrict__ C,           // [M,N]
              int M, int N, int K)
{
    __shared__ float As[BKK][BM + 4];
    __shared__ float Bs[BKK][BN + 4];

    const int tid = threadIdx.x;
    const int m0 = blockIdx.y * BM;
    const int n0 = blockIdx.x * BN;
    const int tr = tid >> 4;    // 0..15
    const int tc = tid & 15;    // 0..15

    float acc[8][8];
    #pragma unroll
    for (int i = 0; i < 8; i++)
        #pragma unroll
        for (int j = 0; j < 8; j++) acc[i][j] = 0.f;

    for (int k0 = 0; k0 < K; k0 += BKK) {
        // Load + transpose A tile (128x16) and W tile (128x16)
        #pragma unroll
        for (int l = 0; l < 2; l++) {
            int idx = tid + l * 256;           // 0..511
            int row = idx >> 2;                // 0..127
            int kc  = (idx & 3) * 4;           // 0,4,8,12
            float4 va = *(const float4*)(A + (size_t)(m0 + row) * K + k0 + kc);
            As[kc + 0][row] = va.x;
            As[kc + 1][row] = va.y;
            As[kc + 2][row] = va.z;
            As[kc + 3][row] = va.w;
            float4 vb = *(const float4*)(W + (size_t)(n0 + row) * K + k0 + kc);
            Bs[kc + 0][row] = vb.x;
            Bs[kc + 1][row] = vb.y;
            Bs[kc + 2][row] = vb.z;
            Bs[kc + 3][row] = vb.w;
        }
        __syncthreads();

        #pragma unroll
        for (int kk = 0; kk < BKK; kk++) {
            float4 a0 = *(const float4*)&As[kk][tr * 8];
            float4 a1 = *(const float4*)&As[kk][tr * 8 + 4];
            float4 b0 = *(const float4*)&Bs[kk][tc * 8];
            float4 b1 = *(const float4*)&Bs[kk][tc * 8 + 4];
            float a[8] = {a0.x, a0.y, a0.z, a0.w, a1.x, a1.y, a1.z, a1.w};
            float b[8] = {b0.x, b0.y, b0.z, b0.w, b1.x, b1.y, b1.z, b1.w};
            #pragma unroll
            for (int i = 0; i < 8; i++)
                #pragma unroll
                for (int j = 0; j < 8; j++)
                    acc[i][j] += a[i] * b[j];
        }
        __syncthreads();
    }

    // Epilogue: bias (+ residual)
    #pragma unroll
    for (int i = 0; i < 8; i++) {
        int m = m0 + tr * 8 + i;
        #pragma unroll
        for (int j = 0; j < 8; j += 4) {
            int n = n0 + tc * 8 + j;
            float4 bv = *(const float4*)(bias + n);
            float4 o;
            o.x = acc[i][j + 0] + bv.x;
            o.y = acc[i][j + 1] + bv.y;
            o.z = acc[i][j + 2] + bv.z;
            o.w = acc[i][j + 3] + bv.w;
            if (resid) {
                float4 r = *(const float4*)(resid + (size_t)m * N + n);
                o.x += r.x; o.y += r.y; o.z += r.z; o.w += r.w;
            }
            *(float4*)(C + (size_t)m * N + n) = o;
        }
    }
}

// ---------------------------------------------------------------------------
// Fused: depthwise causal conv(4) + SiLU + gate dot + scaling + z-gate.
// One block per (batch, 8-timestep chunk); 256 threads, 8 channels each.
//   xc[c]  = silu( conv_b[c] + sum_j conv_w[c,j]*xi[t-3+j, c] )
//   gate   = sigmoid( sum_c xc[c]*wbar[c] )
//   y[c]   = xc[c] * (gate + D[c]) * silu(z[c])
// ---------------------------------------------------------------------------
#define TT 8

__global__ void fused_mid_k(const float* __restrict__ conv_w, // [DI*4]
                            const float* __restrict__ conv_b, // [DI]
                            const float* __restrict__ Dp)     // [DI]
{
    __shared__ float red[256];
    const int b   = blockIdx.y;
    const int t0  = blockIdx.x * TT;
    const int tid = threadIdx.x;

    for (int tt = 0; tt < TT; tt++) {
        const int t = t0 + tt;
        const size_t row = (size_t)b * TD + t;

        float xc_reg[8];
        float partial = 0.f;
        #pragma unroll
        for (int i = 0; i < 8; i++) {
            const int c = tid + i * 256;
            float a = conv_b[c];
            #pragma unroll
            for (int j = 0; j < 4; j++) {
                int ts = t - 3 + j;
                if (ts >= 0)
                    a += conv_w[c * 4 + j] * g_xz[((size_t)b * TD + ts) * (2 * DI) + c];
            }
            float xc = a / (1.f + expf(-a));     // silu
            xc_reg[i] = xc;
            partial += xc * g_wbar[c];
        }

        red[tid] = partial;
        __syncthreads();
        #pragma unroll
        for (int off = 128; off >= 1; off >>= 1) {
            if (tid < off) red[tid] += red[tid + off];
            __syncthreads();
        }
        const float gate = 1.f / (1.f + expf(-red[0]));
        __syncthreads();   // protect red[] before next iteration's writes

        #pragma unroll
        for (int i = 0; i < 8; i++) {
            const int c = tid + i * 256;
            float z  = g_xz[row * (2 * DI) + DI + c];
            float sz = z / (1.f + expf(-z));
            g_y[row * DI + c] = xc_reg[i] * (gate + Dp[c]) * sz;
        }
    }
}

// ---------------------------------------------------------------------------
extern "C" void kernel_launch(void* const* d_in, const int* in_sizes, int n_in,
                              void* d_out, int out_size)
{
    const float* x       = (const float*)d_in[0];
    const float* norm_w  = (const float*)d_in[1];
    const float* norm_b  = (const float*)d_in[2];
    const float* in_w    = (const float*)d_in[3];
    const float* in_b    = (const float*)d_in[4];
    const float* conv_w  = (const float*)d_in[5];
    const float* conv_b  = (const float*)d_in[6];
    const float* xproj_w = (const float*)d_in[7];
    // d_in[8] = A_log : dead in the reference computation
    const float* Dp      = (const float*)d_in[9];
    const float* out_w   = (const float*)d_in[10];
    const float* out_b   = (const float*)d_in[11];
    float* out = (float*)d_out;

    float *xn_p, *xz_p, *y_p;
    cudaGetSymbolAddress((void**)&xn_p, g_xn);
    cudaGetSymbolAddress((void**)&xz_p, g_xz);
    cudaGetSymbolAddress((void**)&y_p,  g_y);

    compute_wbar_k<<<(DI + 255) / 256, 256>>>(xproj_w);
    layernorm_k<<<(int)MROWS, 256>>>(x, norm_w, norm_b);

    // xz = xn @ in_w.T + in_b   (M=16384, N=4096, K=1024)
    // N = 2*DI = 4096  ->  grid.x = 4096/BN = 32   (was 64: OOB weight reads +
    // epilogue writes aliasing the next row of g_xz -> rel_err 0.51)
    sgemm_tn<<<dim3((2 * DI) / BN, (int)MROWS / BM), 256>>>(
        xn_p, in_w, in_b, nullptr, xz_p, (int)MROWS, 2 * DI, DM);

    // conv + silu + gate + z-gate  ->  g_y
    fused_mid_k<<<dim3(TD / TT, BD), 256>>>(conv_w, conv_b, Dp);

    // out = y @ out_w.T + out_b + x   (M=16384, N=1024, K=2048)
    sgemm_tn<<<dim3(DM / BN, (int)MROWS / BM), 256>>>(
        y_p, out_w, out_b, x, out, (int)MROWS, DM, DI);
}

// round 7
// speedup vs baseline: 1.7027x; 1.7027x over previous
#include <cuda_runtime.h>
#include <math.h>
#include <stdint.h>

// Problem constants
static constexpr int  BD = 4;
static constexpr int  TD = 4096;
static constexpr int  DM = 1024;           // d_model
static constexpr int  DI = 2048;           // d_inner
static constexpr size_t MROWS = (size_t)BD * TD;   // 16384

// Scratch
__device__ float g_xn[MROWS * DM];
__device__ float g_xz[MROWS * 2 * DI];
__device__ float g_y [MROWS * DI];
__device__ float g_wbar[DI];

// ===========================================================================
// PTX helpers (sm_80-class: ldmatrix + mma.sync — valid at base sm_103 target)
// ===========================================================================
__device__ __forceinline__ uint32_t smem_u32(const void* p) {
    uint32_t a;
    asm("{ .reg .u64 t; cvta.to.shared.u64 t, %1; cvt.u32.u64 %0, t; }"
        : "=r"(a) : "l"(p));
    return a;
}

__device__ __forceinline__ void ldsm_x4(uint32_t* r, uint32_t addr) {
    asm volatile("ldmatrix.sync.aligned.m8n8.x4.shared.b16 {%0,%1,%2,%3}, [%4];"
                 : "=r"(r[0]), "=r"(r[1]), "=r"(r[2]), "=r"(r[3]) : "r"(addr));
}

__device__ __forceinline__ void mma_bf16(float* d, const uint32_t* a,
                                         uint32_t b0, uint32_t b1) {
    asm volatile(
        "mma.sync.aligned.m16n8k16.row.col.f32.bf16.bf16.f32 "
        "{%0,%1,%2,%3}, {%4,%5,%6,%7}, {%8,%9}, {%0,%1,%2,%3};"
        : "+f"(d[0]), "+f"(d[1]), "+f"(d[2]), "+f"(d[3])
        : "r"(a[0]), "r"(a[1]), "r"(a[2]), "r"(a[3]), "r"(b0), "r"(b1));
}

// pack two fp32 -> bf16x2 (lo in low half, hi in high half)
__device__ __forceinline__ uint32_t pack_bf16x2(float lo, float hi) {
    uint32_t d;
    asm("cvt.rn.bf16x2.f32 %0, %1, %2;" : "=r"(d) : "f"(hi), "f"(lo));
    return d;
}

// ===========================================================================
// HMMA GEMM: C[m,n] = sum_k A[m,k]*W[n,k] + bias[n] (+resid[m,n])
// BM=128, BN=128, BK=32; bf16 3-term split (hi*hi + lo*hi + hi*lo).
// SMEM rows padded to 80B (odd multiple of 16B) -> conflict-free ldmatrix.
// ===========================================================================
#define G_BM 128
#define G_BN 128
#define G_BK 32
#define ROWB 80                            // bytes per smem row (32 bf16 + pad)
static constexpr int TILE_B = 128 * ROWB;  // 10240 bytes per tile

__global__ __launch_bounds__(256, 1)
void gemm_hmma_x3(const float* __restrict__ A,
                  const float* __restrict__ W,
                  const float* __restrict__ bias,
                  const float* __restrict__ resid,
                  float* __restrict__ C,
                  int N, int K)
{
    __shared__ __align__(256) unsigned char sm[4 * TILE_B];  // AH | AL | BH | BL
    const uint32_t sb = smem_u32(sm);
    const uint32_t AH = 0, AL = TILE_B, BH = 2 * TILE_B, BL = 3 * TILE_B;

    const int tid  = threadIdx.x;
    const int wid  = tid >> 5, lane = tid & 31;
    const int wm   = wid & 3;          // warp m-block (32 rows)
    const int wn   = wid >> 2;         // warp n-block (64 cols)
    const int m0   = blockIdx.y * G_BM;
    const int n0   = blockIdx.x * G_BN;

    // loader mapping: 2 threads per 128-row, each covers 16 floats (half row)
    const int lrow = tid >> 1;
    const int lcol = (tid & 1) * 16;   // float offset within the 32-wide row

    // ldmatrix per-lane offset (row within 16-block, k-half)
    const uint32_t frag_off = (uint32_t)((lane & 15) * ROWB + (lane >> 4) * 16);

    float acc[2][8][4];
    #pragma unroll
    for (int i = 0; i < 2; i++)
        #pragma unroll
        for (int j = 0; j < 8; j++)
            #pragma unroll
            for (int q = 0; q < 4; q++) acc[i][j][q] = 0.f;

    float4 pa[4], pb[4];
    const float* Arow = A + (size_t)(m0 + lrow) * K + lcol;
    const float* Wrow = W + (size_t)(n0 + lrow) * K + lcol;

    // prologue: LDG tile 0
    #pragma unroll
    for (int j = 0; j < 4; j++) {
        pa[j] = *(const float4*)(Arow + j * 4);
        pb[j] = *(const float4*)(Wrow + j * 4);
    }

    const int KC = K / G_BK;
    for (int it = 0; it < KC; it++) {
        // ---- STS with bf16 hi/lo split ----
        const uint32_t rowbase = (uint32_t)(lrow * ROWB + lcol * 2);
        #pragma unroll
        for (int j = 0; j < 4; j++) {
            float4 v = pa[j];
            uint32_t h0 = pack_bf16x2(v.x, v.y), h1 = pack_bf16x2(v.z, v.w);
            float r0 = v.x - __uint_as_float(h0 << 16);
            float r1 = v.y - __uint_as_float(h0 & 0xFFFF0000u);
            float r2 = v.z - __uint_as_float(h1 << 16);
            float r3 = v.w - __uint_as_float(h1 & 0xFFFF0000u);
            uint32_t l0 = pack_bf16x2(r0, r1), l1 = pack_bf16x2(r2, r3);
            uint32_t off = rowbase + j * 8;
            *(uint2*)(sm + AH + off) = make_uint2(h0, h1);
            *(uint2*)(sm + AL + off) = make_uint2(l0, l1);

            v = pb[j];
            h0 = pack_bf16x2(v.x, v.y); h1 = pack_bf16x2(v.z, v.w);
            r0 = v.x - __uint_as_float(h0 << 16);
            r1 = v.y - __uint_as_float(h0 & 0xFFFF0000u);
            r2 = v.z - __uint_as_float(h1 << 16);
            r3 = v.w - __uint_as_float(h1 & 0xFFFF0000u);
            l0 = pack_bf16x2(r0, r1); l1 = pack_bf16x2(r2, r3);
            *(uint2*)(sm + BH + off) = make_uint2(h0, h1);
            *(uint2*)(sm + BL + off) = make_uint2(l0, l1);
        }
        __syncthreads();

        // ---- prefetch next tile (overlapped with MMA work) ----
        if (it + 1 < KC) {
            const float* An = Arow + (it + 1) * G_BK;
            const float* Wn = Wrow + (it + 1) * G_BK;
            #pragma unroll
            for (int j = 0; j < 4; j++) {
                pa[j] = *(const float4*)(An + j * 4);
                pb[j] = *(const float4*)(Wn + j * 4);
            }
        }

        // ---- compute: 2 k16 steps x 48 MMAs ----
        #pragma unroll
        for (int kc = 0; kc < 2; kc++) {
            uint32_t ah[2][4], al[2][4], bh[4][4], bl[4][4];
            #pragma unroll
            for (int mi = 0; mi < 2; mi++) {
                uint32_t base = (uint32_t)((wm * 32 + mi * 16) * ROWB + kc * 32) + frag_off;
                ldsm_x4(ah[mi], sb + AH + base);
                ldsm_x4(al[mi], sb + AL + base);
            }
            #pragma unroll
            for (int nj = 0; nj < 4; nj++) {
                uint32_t base = (uint32_t)((wn * 64 + nj * 16) * ROWB + kc * 32) + frag_off;
                ldsm_x4(bh[nj], sb + BH + base);
                ldsm_x4(bl[nj], sb + BL + base);
            }
            #pragma unroll
            for (int mi = 0; mi < 2; mi++)
                #pragma unroll
                for (int nj = 0; nj < 4; nj++)
                    #pragma unroll
                    for (int h = 0; h < 2; h++) {
                        float* d = acc[mi][nj * 2 + h];
                        mma_bf16(d, ah[mi], bh[nj][h], bh[nj][h + 2]);
                        mma_bf16(d, al[mi], bh[nj][h], bh[nj][h + 2]);
                        mma_bf16(d, ah[mi], bl[nj][h], bl[nj][h + 2]);
                    }
        }
        __syncthreads();
    }

    // ---- epilogue ----
    const int lg = lane >> 2;          // 0..7  (row within 8)
    const int lq = lane & 3;           // col pair selector
    #pragma unroll
    for (int mi = 0; mi < 2; mi++) {
        const int mbase = m0 + wm * 32 + mi * 16 + lg;
        #pragma unroll
        for (int ni = 0; ni < 8; ni++) {
            const int n = n0 + wn * 64 + ni * 8 + lq * 2;
            float2 bv = *(const float2*)(bias + n);
            float* a = acc[mi][ni];

            float2 o0 = make_float2(a[0] + bv.x, a[1] + bv.y);
            float2 o1 = make_float2(a[2] + bv.x, a[3] + bv.y);
            if (resid) {
                float2 r0 = *(const float2*)(resid + (size_t)mbase * N + n);
                float2 r1 = *(const float2*)(resid + (size_t)(mbase + 8) * N + n);
                o0.x += r0.x; o0.y += r0.y;
                o1.x += r1.x; o1.y += r1.y;
            }
            *(float2*)(C + (size_t)mbase * N + n)       = o0;
            *(float2*)(C + (size_t)(mbase + 8) * N + n) = o1;
        }
    }
}

// ---------------------------------------------------------------------------
// wbar[c] = (1/16) * sum_s xproj_w[17+s, c]
// ---------------------------------------------------------------------------
__global__ void compute_wbar_k(const float* __restrict__ xproj_w)
{
    int c = blockIdx.x * blockDim.x + threadIdx.x;
    if (c < DI) {
        float s = 0.f;
        #pragma unroll
        for (int k = 0; k < 16; k++)
            s += xproj_w[(size_t)(17 + k) * DI + c];
        g_wbar[c] = s * (1.f / 16.f);
    }
}

// ---------------------------------------------------------------------------
// LayerNorm: one block per row (1024 elems)
// ---------------------------------------------------------------------------
__global__ void layernorm_k(const float* __restrict__ x,
                            const float* __restrict__ w,
                            const float* __restrict__ b)
{
    __shared__ float2 red[256];
    size_t row = blockIdx.x;
    int tid = threadIdx.x;

    const float4* xr = (const float4*)(x + row * DM);
    float4 v = xr[tid];
    float s  = v.x + v.y + v.z + v.w;
    float ss = v.x * v.x + v.y * v.y + v.z * v.z + v.w * v.w;
    red[tid] = make_float2(s, ss);
    __syncthreads();
    #pragma unroll
    for (int off = 128; off >= 1; off >>= 1) {
        if (tid < off) {
            red[tid].x += red[tid + off].x;
            red[tid].y += red[tid + off].y;
        }
        __syncthreads();
    }
    float mu  = red[0].x * (1.f / DM);
    float var = red[0].y * (1.f / DM) - mu * mu;
    float rstd = rsqrtf(var + 1e-5f);

    int c = tid * 4;
    const float4 wv = *(const float4*)(w + c);
    const float4 bv = *(const float4*)(b + c);
    float4 o;
    o.x = (v.x - mu) * rstd * wv.x + bv.x;
    o.y = (v.y - mu) * rstd * wv.y + bv.y;
    o.z = (v.z - mu) * rstd * wv.z + bv.z;
    o.w = (v.w - mu) * rstd * wv.w + bv.w;
    ((float4*)(g_xn + row * DM))[tid] = o;
}

// ---------------------------------------------------------------------------
// Fused mid: causal depthwise conv(4) + SiLU + gate + z-gate.
// Register conv-window rotation: xi read once per (t, c).
// ---------------------------------------------------------------------------
#define TT 32

__global__ __launch_bounds__(256)
void fused_mid_k(const float* __restrict__ conv_w,
                 const float* __restrict__ conv_b,
                 const float* __restrict__ Dp)
{
    __shared__ float red[8];
    __shared__ float gate_sh;
    const int b   = blockIdx.y;
    const int t0  = blockIdx.x * TT;
    const int tid = threadIdx.x;
    const int lane = tid & 31, wrp = tid >> 5;
    const int c0 = tid * 8;

    float cw0[8], cw1[8], cw2[8], cw3[8], cb[8], wb[8], dd[8];
    #pragma unroll
    for (int i = 0; i < 8; i++) {
        float4 q = *(const float4*)(conv_w + (size_t)(c0 + i) * 4);
        cw0[i] = q.x; cw1[i] = q.y; cw2[i] = q.z; cw3[i] = q.w;
        cb[i] = conv_b[c0 + i];
        wb[i] = g_wbar[c0 + i];
        dd[i] = Dp[c0 + i];
    }

    float w0[8], w1[8], w2[8];
    #pragma unroll
    for (int j = 0; j < 3; j++) {
        int t = t0 - 3 + j;
        float* dst = (j == 0) ? w0 : (j == 1) ? w1 : w2;
        if (t >= 0) {
            const float* src = g_xz + ((size_t)b * TD + t) * (2 * DI) + c0;
            float4 a = *(const float4*)src;
            float4 c = *(const float4*)(src + 4);
            dst[0]=a.x; dst[1]=a.y; dst[2]=a.z; dst[3]=a.w;
            dst[4]=c.x; dst[5]=c.y; dst[6]=c.z; dst[7]=c.w;
        } else {
            #pragma unroll
            for (int i = 0; i < 8; i++) dst[i] = 0.f;
        }
    }

    for (int tt = 0; tt < TT; tt++) {
        const int t = t0 + tt;
        const size_t rb = ((size_t)b * TD + t) * (2 * DI);

        float cur[8];
        {
            const float* src = g_xz + rb + c0;
            float4 a = *(const float4*)src;
            float4 c = *(const float4*)(src + 4);
            cur[0]=a.x; cur[1]=a.y; cur[2]=a.z; cur[3]=a.w;
            cur[4]=c.x; cur[5]=c.y; cur[6]=c.z; cur[7]=c.w;
        }

        float xc[8], partial = 0.f;
        #pragma unroll
        for (int i = 0; i < 8; i++) {
            float a = cb[i] + w0[i]*cw0[i] + w1[i]*cw1[i] + w2[i]*cw2[i] + cur[i]*cw3[i];
            float sg = 1.f / (1.f + __expf(-a));
            xc[i] = a * sg;
            partial += xc[i] * wb[i];
        }

        #pragma unroll
        for (int off = 16; off >= 1; off >>= 1)
            partial += __shfl_xor_sync(0xffffffffu, partial, off);
        if (lane == 0) red[wrp] = partial;
        __syncthreads();
        if (tid == 0) {
            float s = 0.f;
            #pragma unroll
            for (int k = 0; k < 8; k++) s += red[k];
            gate_sh = 1.f / (1.f + __expf(-s));
        }
        __syncthreads();
        const float gate = gate_sh;

        float zv[8];
        {
            const float* src = g_xz + rb + DI + c0;
            float4 a = *(const float4*)src;
            float4 c = *(const float4*)(src + 4);
            zv[0]=a.x; zv[1]=a.y; zv[2]=a.z; zv[3]=a.w;
            zv[4]=c.x; zv[5]=c.y; zv[6]=c.z; zv[7]=c.w;
        }
        float out[8];
        #pragma unroll
        for (int i = 0; i < 8; i++) {
            float sz = zv[i] / (1.f + __expf(-zv[i]));
            out[i] = xc[i] * (gate + dd[i]) * sz;
        }
        float* dst = g_y + ((size_t)b * TD + t) * DI + c0;
        *(float4*)dst       = make_float4(out[0], out[1], out[2], out[3]);
        *(float4*)(dst + 4) = make_float4(out[4], out[5], out[6], out[7]);

        #pragma unroll
        for (int i = 0; i < 8; i++) { w0[i] = w1[i]; w1[i] = w2[i]; w2[i] = cur[i]; }
    }
}

// ---------------------------------------------------------------------------
extern "C" void kernel_launch(void* const* d_in, const int* in_sizes, int n_in,
                              void* d_out, int out_size)
{
    const float* x       = (const float*)d_in[0];
    const float* norm_w  = (const float*)d_in[1];
    const float* norm_b  = (const float*)d_in[2];
    const float* in_w    = (const float*)d_in[3];
    const float* in_b    = (const float*)d_in[4];
    const float* conv_w  = (const float*)d_in[5];
    const float* conv_b  = (const float*)d_in[6];
    const float* xproj_w = (const float*)d_in[7];
    const float* Dp      = (const float*)d_in[9];
    const float* out_w   = (const float*)d_in[10];
    const float* out_b   = (const float*)d_in[11];
    float* out = (float*)d_out;

    float *xn_p, *xz_p, *y_p;
    cudaGetSymbolAddress((void**)&xn_p, g_xn);
    cudaGetSymbolAddress((void**)&xz_p, g_xz);
    cudaGetSymbolAddress((void**)&y_p,  g_y);

    compute_wbar_k<<<(DI + 255) / 256, 256>>>(xproj_w);
    layernorm_k<<<(int)MROWS, 256>>>(x, norm_w, norm_b);

    // GEMM1: xz = xn @ in_w.T + in_b   (M=16384, N=4096, K=1024)
    gemm_hmma_x3<<<dim3((2 * DI) / G_BN, (int)MROWS / G_BM), 256>>>(
        xn_p, in_w, in_b, nullptr, xz_p, 2 * DI, DM);

    // conv + silu + gate + z-gate -> g_y
    fused_mid_k<<<dim3(TD / TT, BD), 256>>>(conv_w, conv_b, Dp);

    // GEMM2: out = y @ out_w.T + out_b + x   (M=16384, N=1024, K=2048)
    gemm_hmma_x3<<<dim3(DM / G_BN, (int)MROWS / G_BM), 256>>>(
        y_p, out_w, out_b, x, out, DM, DI);
}

// round 8
// speedup vs baseline: 2.0052x; 1.1777x over previous
#include <cuda_runtime.h>
#include <cuda_bf16.h>
#include <math.h>
#include <stdint.h>

// Problem constants
static constexpr int  BD = 4;
static constexpr int  TD = 4096;
static constexpr int  DM = 1024;           // d_model
static constexpr int  DI = 2048;           // d_inner
static constexpr size_t MROWS = (size_t)BD * TD;   // 16384

// Scratch planes (bf16 hi/lo split, produced once per launch)
__device__ __nv_bfloat16 g_xn_h[MROWS * DM];
__device__ __nv_bfloat16 g_xn_l[MROWS * DM];
__device__ float         g_xz  [MROWS * 2 * DI];
__device__ __nv_bfloat16 g_y_h [MROWS * DI];
__device__ __nv_bfloat16 g_y_l [MROWS * DI];
__device__ __nv_bfloat16 g_w1h[(size_t)(2 * DI) * DM];
__device__ __nv_bfloat16 g_w1l[(size_t)(2 * DI) * DM];
__device__ __nv_bfloat16 g_w2h[(size_t)DM * DI];
__device__ __nv_bfloat16 g_w2l[(size_t)DM * DI];
__device__ float g_wbar[DI];

// ===========================================================================
// PTX helpers (sm_80-class — valid at base sm_103 target)
// ===========================================================================
__device__ __forceinline__ uint32_t smem_u32(const void* p) {
    uint32_t a;
    asm("{ .reg .u64 t; cvta.to.shared.u64 t, %1; cvt.u32.u64 %0, t; }"
        : "=r"(a) : "l"(p));
    return a;
}
__device__ __forceinline__ void ldsm_x4(uint32_t* r, uint32_t addr) {
    asm volatile("ldmatrix.sync.aligned.m8n8.x4.shared.b16 {%0,%1,%2,%3}, [%4];"
                 : "=r"(r[0]), "=r"(r[1]), "=r"(r[2]), "=r"(r[3]) : "r"(addr));
}
__device__ __forceinline__ void mma_bf16(float* d, const uint32_t* a,
                                         uint32_t b0, uint32_t b1) {
    asm volatile(
        "mma.sync.aligned.m16n8k16.row.col.f32.bf16.bf16.f32 "
        "{%0,%1,%2,%3}, {%4,%5,%6,%7}, {%8,%9}, {%0,%1,%2,%3};"
        : "+f"(d[0]), "+f"(d[1]), "+f"(d[2]), "+f"(d[3])
        : "r"(a[0]), "r"(a[1]), "r"(a[2]), "r"(a[3]), "r"(b0), "r"(b1));
}
// pack two fp32 -> bf16x2 (first arg in LOW half)
__device__ __forceinline__ uint32_t pack_bf16x2(float lo, float hi) {
    uint32_t d;
    asm("cvt.rn.bf16x2.f32 %0, %1, %2;" : "=r"(d) : "f"(hi), "f"(lo));
    return d;
}
#define CP_ASYNC16(dst, src) \
    asm volatile("cp.async.cg.shared.global [%0], [%1], 16;" \
                 :: "r"(dst), "l"(src) : "memory")
#define CP_COMMIT() asm volatile("cp.async.commit_group;" ::: "memory")
#define CP_WAIT1()  asm volatile("cp.async.wait_group 1;" ::: "memory")
#define CP_WAIT0()  asm volatile("cp.async.wait_group 0;" ::: "memory")

// ===========================================================================
// HMMA GEMM, bf16 3-term split, pre-split operands, cp.async 2-stage pipeline
// BM=128, BN=128, BK=32. SMEM rows 80B -> conflict-free ldmatrix, no swizzle.
// ===========================================================================
#define G_BM 128
#define G_BN 128
#define G_BK 32
#define ROWB 80
static constexpr int TILE_B  = 128 * ROWB;      // 10240 B per tile
static constexpr int STAGE_B = 4 * TILE_B;      // AH|AL|BH|BL = 40960 B
static constexpr int GEMM_SMEM = 2 * STAGE_B;   // 81920 B

__global__ __launch_bounds__(256, 1)
void gemm_hmma_x3(const __nv_bfloat16* __restrict__ Ah,
                  const __nv_bfloat16* __restrict__ Al,
                  const __nv_bfloat16* __restrict__ Wh,
                  const __nv_bfloat16* __restrict__ Wl,
                  const float* __restrict__ bias,
                  const float* __restrict__ resid,
                  float* __restrict__ C,
                  int N, int K)
{
    extern __shared__ __align__(16) unsigned char dsm[];
    const uint32_t sb = smem_u32(dsm);

    const int tid  = threadIdx.x;
    const int wid  = tid >> 5, lane = tid & 31;
    const int wm   = wid & 3;          // warp m-block (32 rows)
    const int wn   = wid >> 2;         // warp n-block (64 cols)
    const int m0   = blockIdx.y * G_BM;
    const int n0   = blockIdx.x * G_BN;

    const uint32_t frag_off = (uint32_t)((lane & 15) * ROWB + (lane >> 4) * 16);

    float acc[2][8][4];
    #pragma unroll
    for (int i = 0; i < 2; i++)
        #pragma unroll
        for (int j = 0; j < 8; j++)
            #pragma unroll
            for (int q = 0; q < 4; q++) acc[i][j][q] = 0.f;

    auto issue = [&](int it) {
        const int k0 = it * G_BK;
        const uint32_t st = sb + (it & 1) * STAGE_B;
        #pragma unroll
        for (int j = 0; j < 2; j++) {
            int t2  = tid + j * 256;           // 0..511
            int row = t2 >> 2;                 // 0..127
            int c16 = t2 & 3;                  // 16B chunk in row
            uint32_t doff = (uint32_t)(row * ROWB + c16 * 16);
            size_t ao = (size_t)(m0 + row) * K + k0 + c16 * 8;
            size_t bo = (size_t)(n0 + row) * K + k0 + c16 * 8;
            CP_ASYNC16(st + 0 * TILE_B + doff, Ah + ao);
            CP_ASYNC16(st + 1 * TILE_B + doff, Al + ao);
            CP_ASYNC16(st + 2 * TILE_B + doff, Wh + bo);
            CP_ASYNC16(st + 3 * TILE_B + doff, Wl + bo);
        }
    };

    const int KC = K / G_BK;
    issue(0); CP_COMMIT();

    for (int it = 0; it < KC; it++) {
        if (it + 1 < KC) { issue(it + 1); CP_COMMIT(); CP_WAIT1(); }
        else             { CP_WAIT0(); }
        __syncthreads();                       // stage (it&1) visible to all

        const uint32_t st = sb + (it & 1) * STAGE_B;
        #pragma unroll
        for (int kc = 0; kc < 2; kc++) {
            uint32_t ah[2][4], al[2][4], bh[4][4], bl[4][4];
            #pragma unroll
            for (int mi = 0; mi < 2; mi++) {
                uint32_t base = (uint32_t)((wm * 32 + mi * 16) * ROWB + kc * 32) + frag_off;
                ldsm_x4(ah[mi], st + 0 * TILE_B + base);
                ldsm_x4(al[mi], st + 1 * TILE_B + base);
            }
            #pragma unroll
            for (int nj = 0; nj < 4; nj++) {
                uint32_t base = (uint32_t)((wn * 64 + nj * 16) * ROWB + kc * 32) + frag_off;
                ldsm_x4(bh[nj], st + 2 * TILE_B + base);
                ldsm_x4(bl[nj], st + 3 * TILE_B + base);
            }
            // term-outermost: same-acc reuse distance = 16 MMAs
            #pragma unroll
            for (int mi = 0; mi < 2; mi++)
                #pragma unroll
                for (int nj = 0; nj < 4; nj++)
                    #pragma unroll
                    for (int h = 0; h < 2; h++)
                        mma_bf16(acc[mi][nj * 2 + h], ah[mi], bh[nj][h], bh[nj][h + 2]);
            #pragma unroll
            for (int mi = 0; mi < 2; mi++)
                #pragma unroll
                for (int nj = 0; nj < 4; nj++)
                    #pragma unroll
                    for (int h = 0; h < 2; h++)
                        mma_bf16(acc[mi][nj * 2 + h], al[mi], bh[nj][h], bh[nj][h + 2]);
            #pragma unroll
            for (int mi = 0; mi < 2; mi++)
                #pragma unroll
                for (int nj = 0; nj < 4; nj++)
                    #pragma unroll
                    for (int h = 0; h < 2; h++)
                        mma_bf16(acc[mi][nj * 2 + h], ah[mi], bl[nj][h], bl[nj][h + 2]);
        }
        __syncthreads();                       // all reads done before overwrite
    }

    // ---- epilogue ----
    const int lg = lane >> 2;
    const int lq = lane & 3;
    #pragma unroll
    for (int mi = 0; mi < 2; mi++) {
        const int mbase = m0 + wm * 32 + mi * 16 + lg;
        #pragma unroll
        for (int ni = 0; ni < 8; ni++) {
            const int n = n0 + wn * 64 + ni * 8 + lq * 2;
            float2 bv = *(const float2*)(bias + n);
            float* a = acc[mi][ni];
            float2 o0 = make_float2(a[0] + bv.x, a[1] + bv.y);
            float2 o1 = make_float2(a[2] + bv.x, a[3] + bv.y);
            if (resid) {
                float2 r0 = *(const float2*)(resid + (size_t)mbase * N + n);
                float2 r1 = *(const float2*)(resid + (size_t)(mbase + 8) * N + n);
                o0.x += r0.x; o0.y += r0.y;
                o1.x += r1.x; o1.y += r1.y;
            }
            *(float2*)(C + (size_t)mbase * N + n)       = o0;
            *(float2*)(C + (size_t)(mbase + 8) * N + n) = o1;
        }
    }
}

// ---------------------------------------------------------------------------
// Weight hi/lo split (runs every launch; elementwise, tiny)
// ---------------------------------------------------------------------------
__global__ void wsplit_k(const float* __restrict__ w,
                         __nv_bfloat16* __restrict__ wh,
                         __nv_bfloat16* __restrict__ wl, int n4)
{
    int i = blockIdx.x * blockDim.x + threadIdx.x;
    if (i < n4) {
        float4 v = *(const float4*)(w + (size_t)i * 4);
        uint32_t h01 = pack_bf16x2(v.x, v.y), h23 = pack_bf16x2(v.z, v.w);
        float r0 = v.x - __uint_as_float(h01 << 16);
        float r1 = v.y - __uint_as_float(h01 & 0xFFFF0000u);
        float r2 = v.z - __uint_as_float(h23 << 16);
        float r3 = v.w - __uint_as_float(h23 & 0xFFFF0000u);
        *(uint2*)(wh + (size_t)i * 4) = make_uint2(h01, h23);
        *(uint2*)(wl + (size_t)i * 4) = make_uint2(pack_bf16x2(r0, r1), pack_bf16x2(r2, r3));
    }
}

// ---------------------------------------------------------------------------
// wbar[c] = (1/16) * sum_s xproj_w[17+s, c]
// ---------------------------------------------------------------------------
__global__ void compute_wbar_k(const float* __restrict__ xproj_w)
{
    int c = blockIdx.x * blockDim.x + threadIdx.x;
    if (c < DI) {
        float s = 0.f;
        #pragma unroll
        for (int k = 0; k < 16; k++)
            s += xproj_w[(size_t)(17 + k) * DI + c];
        g_wbar[c] = s * (1.f / 16.f);
    }
}

// ---------------------------------------------------------------------------
// LayerNorm -> bf16 hi/lo planes
// ---------------------------------------------------------------------------
__global__ void layernorm_k(const float* __restrict__ x,
                            const float* __restrict__ w,
                            const float* __restrict__ b)
{
    __shared__ float2 red[256];
    size_t row = blockIdx.x;
    int tid = threadIdx.x;

    const float4* xr = (const float4*)(x + row * DM);
    float4 v = xr[tid];
    float s  = v.x + v.y + v.z + v.w;
    float ss = v.x * v.x + v.y * v.y + v.z * v.z + v.w * v.w;
    red[tid] = make_float2(s, ss);
    __syncthreads();
    #pragma unroll
    for (int off = 128; off >= 1; off >>= 1) {
        if (tid < off) {
            red[tid].x += red[tid + off].x;
            red[tid].y += red[tid + off].y;
        }
        __syncthreads();
    }
    float mu  = red[0].x * (1.f / DM);
    float var = red[0].y * (1.f / DM) - mu * mu;
    float rstd = rsqrtf(var + 1e-5f);

    int c = tid * 4;
    const float4 wv = *(const float4*)(w + c);
    const float4 bv = *(const float4*)(b + c);
    float4 o;
    o.x = (v.x - mu) * rstd * wv.x + bv.x;
    o.y = (v.y - mu) * rstd * wv.y + bv.y;
    o.z = (v.z - mu) * rstd * wv.z + bv.z;
    o.w = (v.w - mu) * rstd * wv.w + bv.w;

    uint32_t h01 = pack_bf16x2(o.x, o.y), h23 = pack_bf16x2(o.z, o.w);
    float r0 = o.x - __uint_as_float(h01 << 16);
    float r1 = o.y - __uint_as_float(h01 & 0xFFFF0000u);
    float r2 = o.z - __uint_as_float(h23 << 16);
    float r3 = o.w - __uint_as_float(h23 & 0xFFFF0000u);
    *(uint2*)(g_xn_h + row * DM + c) = make_uint2(h01, h23);
    *(uint2*)(g_xn_l + row * DM + c) = make_uint2(pack_bf16x2(r0, r1), pack_bf16x2(r2, r3));
}

// ---------------------------------------------------------------------------
// Fused mid: conv(4) + SiLU + gate + z-gate -> bf16 hi/lo planes of y
// ---------------------------------------------------------------------------
#define TT 32

__global__ __launch_bounds__(256)
void fused_mid_k(const float* __restrict__ conv_w,
                 const float* __restrict__ conv_b,
                 const float* __restrict__ Dp)
{
    __shared__ float red[8];
    __shared__ float gate_sh;
    const int b   = blockIdx.y;
    const int t0  = blockIdx.x * TT;
    const int tid = threadIdx.x;
    const int lane = tid & 31, wrp = tid >> 5;
    const int c0 = tid * 8;

    float cw0[8], cw1[8], cw2[8], cw3[8], cb[8], wb[8], dd[8];
    #pragma unroll
    for (int i = 0; i < 8; i++) {
        float4 q = *(const float4*)(conv_w + (size_t)(c0 + i) * 4);
        cw0[i] = q.x; cw1[i] = q.y; cw2[i] = q.z; cw3[i] = q.w;
        cb[i] = conv_b[c0 + i];
        wb[i] = g_wbar[c0 + i];
        dd[i] = Dp[c0 + i];
    }

    float w0[8], w1[8], w2[8];
    #pragma unroll
    for (int j = 0; j < 3; j++) {
        int t = t0 - 3 + j;
        float* dst = (j == 0) ? w0 : (j == 1) ? w1 : w2;
        if (t >= 0) {
            const float* src = g_xz + ((size_t)b * TD + t) * (2 * DI) + c0;
            float4 a = *(const float4*)src;
            float4 c = *(const float4*)(src + 4);
            dst[0]=a.x; dst[1]=a.y; dst[2]=a.z; dst[3]=a.w;
            dst[4]=c.x; dst[5]=c.y; dst[6]=c.z; dst[7]=c.w;
        } else {
            #pragma unroll
            for (int i = 0; i < 8; i++) dst[i] = 0.f;
        }
    }

    for (int tt = 0; tt < TT; tt++) {
        const int t = t0 + tt;
        const size_t rb = ((size_t)b * TD + t) * (2 * DI);

        float cur[8];
        {
            const float* src = g_xz + rb + c0;
            float4 a = *(const float4*)src;
            float4 c = *(const float4*)(src + 4);
            cur[0]=a.x; cur[1]=a.y; cur[2]=a.z; cur[3]=a.w;
            cur[4]=c.x; cur[5]=c.y; cur[6]=c.z; cur[7]=c.w;
        }

        float xc[8], partial = 0.f;
        #pragma unroll
        for (int i = 0; i < 8; i++) {
            float a = cb[i] + w0[i]*cw0[i] + w1[i]*cw1[i] + w2[i]*cw2[i] + cur[i]*cw3[i];
            float sg = 1.f / (1.f + __expf(-a));
            xc[i] = a * sg;
            partial += xc[i] * wb[i];
        }

        #pragma unroll
        for (int off = 16; off >= 1; off >>= 1)
            partial += __shfl_xor_sync(0xffffffffu, partial, off);
        if (lane == 0) red[wrp] = partial;
        __syncthreads();
        if (tid == 0) {
            float s = 0.f;
            #pragma unroll
            for (int k = 0; k < 8; k++) s += red[k];
            gate_sh = 1.f / (1.f + __expf(-s));
        }
        __syncthreads();
        const float gate = gate_sh;

        float zv[8];
        {
            const float* src = g_xz + rb + DI + c0;
            float4 a = *(const float4*)src;
            float4 c = *(const float4*)(src + 4);
            zv[0]=a.x; zv[1]=a.y; zv[2]=a.z; zv[3]=a.w;
            zv[4]=c.x; zv[5]=c.y; zv[6]=c.z; zv[7]=c.w;
        }
        float out[8];
        #pragma unroll
        for (int i = 0; i < 8; i++) {
            float sz = zv[i] / (1.f + __expf(-zv[i]));
            out[i] = xc[i] * (gate + dd[i]) * sz;
        }

        uint32_t h[4], l[4];
        #pragma unroll
        for (int q = 0; q < 4; q++) {
            h[q] = pack_bf16x2(out[2 * q], out[2 * q + 1]);
            float ra = out[2 * q]     - __uint_as_float(h[q] << 16);
            float rbq = out[2 * q + 1] - __uint_as_float(h[q] & 0xFFFF0000u);
            l[q] = pack_bf16x2(ra, rbq);
        }
        size_t yo = ((size_t)b * TD + t) * DI + c0;
        *(uint4*)(g_y_h + yo) = make_uint4(h[0], h[1], h[2], h[3]);
        *(uint4*)(g_y_l + yo) = make_uint4(l[0], l[1], l[2], l[3]);

        #pragma unroll
        for (int i = 0; i < 8; i++) { w0[i] = w1[i]; w1[i] = w2[i]; w2[i] = cur[i]; }
    }
}

// ---------------------------------------------------------------------------
extern "C" void kernel_launch(void* const* d_in, const int* in_sizes, int n_in,
                              void* d_out, int out_size)
{
    const float* x       = (const float*)d_in[0];
    const float* norm_w  = (const float*)d_in[1];
    const float* norm_b  = (const float*)d_in[2];
    const float* in_w    = (const float*)d_in[3];
    const float* in_b    = (const float*)d_in[4];
    const float* conv_w  = (const float*)d_in[5];
    const float* conv_b  = (const float*)d_in[6];
    const float* xproj_w = (const float*)d_in[7];
    const float* Dp      = (const float*)d_in[9];
    const float* out_w   = (const float*)d_in[10];
    const float* out_b   = (const float*)d_in[11];
    float* out = (float*)d_out;

    __nv_bfloat16 *xnh, *xnl, *yh, *yl, *w1h, *w1l, *w2h, *w2l;
    float *xz_p;
    cudaGetSymbolAddress((void**)&xnh, g_xn_h);
    cudaGetSymbolAddress((void**)&xnl, g_xn_l);
    cudaGetSymbolAddress((void**)&xz_p, g_xz);
    cudaGetSymbolAddress((void**)&yh, g_y_h);
    cudaGetSymbolAddress((void**)&yl, g_y_l);
    cudaGetSymbolAddress((void**)&w1h, g_w1h);
    cudaGetSymbolAddress((void**)&w1l, g_w1l);
    cudaGetSymbolAddress((void**)&w2h, g_w2h);
    cudaGetSymbolAddress((void**)&w2l, g_w2l);

    static int smem_set = 0;
    if (!smem_set) {
        cudaFuncSetAttribute(gemm_hmma_x3,
                             cudaFuncAttributeMaxDynamicSharedMemorySize, GEMM_SMEM);
        smem_set = 1;
    }

    // weight splits (elementwise, tiny)
    {
        int n4a = (2 * DI) * DM / 4;
        wsplit_k<<<(n4a + 255) / 256, 256>>>(in_w, w1h, w1l, n4a);
        int n4b = DM * DI / 4;
        wsplit_k<<<(n4b + 255) / 256, 256>>>(out_w, w2h, w2l, n4b);
    }
    compute_wbar_k<<<(DI + 255) / 256, 256>>>(xproj_w);
    layernorm_k<<<(int)MROWS, 256>>>(x, norm_w, norm_b);

    // GEMM1: xz = xn @ in_w.T + in_b   (M=16384, N=4096, K=1024)
    gemm_hmma_x3<<<dim3((2 * DI) / G_BN, (int)MROWS / G_BM), 256, GEMM_SMEM>>>(
        xnh, xnl, w1h, w1l, in_b, nullptr, xz_p, 2 * DI, DM);

    // conv + silu + gate + z-gate -> y planes
    fused_mid_k<<<dim3(TD / TT, BD), 256>>>(conv_w, conv_b, Dp);

    // GEMM2: out = y @ out_w.T + out_b + x   (M=16384, N=1024, K=2048)
    gemm_hmma_x3<<<dim3(DM / G_BN, (int)MROWS / G_BM), 256, GEMM_SMEM>>>(
        yh, yl, w2h, w2l, out_b, x, out, DM, DI);
}

// round 9
// speedup vs baseline: 2.0180x; 1.0064x over previous
#include <cuda_runtime.h>
#include <cuda_bf16.h>
#include <math.h>
#include <stdint.h>

// Problem constants
static constexpr int  BD = 4;
static constexpr int  TD = 4096;
static constexpr int  DM = 1024;           // d_model
static constexpr int  DI = 2048;           // d_inner
static constexpr size_t MROWS = (size_t)BD * TD;   // 16384

// Scratch planes (bf16 hi/lo split)
__device__ __nv_bfloat16 g_xn_h[MROWS * DM];
__device__ __nv_bfloat16 g_xn_l[MROWS * DM];
__device__ float         g_xz  [MROWS * 2 * DI];
__device__ __nv_bfloat16 g_y_h [MROWS * DI];
__device__ __nv_bfloat16 g_y_l [MROWS * DI];
__device__ __nv_bfloat16 g_w1h[(size_t)(2 * DI) * DM];
__device__ __nv_bfloat16 g_w1l[(size_t)(2 * DI) * DM];
__device__ __nv_bfloat16 g_w2h[(size_t)DM * DI];
__device__ __nv_bfloat16 g_w2l[(size_t)DM * DI];
__device__ float g_wbar[DI];

// ===========================================================================
// PTX helpers (sm_80-class — valid at base sm_103 target)
// ===========================================================================
__device__ __forceinline__ uint32_t smem_u32(const void* p) {
    uint32_t a;
    asm("{ .reg .u64 t; cvta.to.shared.u64 t, %1; cvt.u32.u64 %0, t; }"
        : "=r"(a) : "l"(p));
    return a;
}
__device__ __forceinline__ void ldsm_x4(uint32_t* r, uint32_t addr) {
    asm volatile("ldmatrix.sync.aligned.m8n8.x4.shared.b16 {%0,%1,%2,%3}, [%4];"
                 : "=r"(r[0]), "=r"(r[1]), "=r"(r[2]), "=r"(r[3]) : "r"(addr));
}
__device__ __forceinline__ void mma_bf16(float* d, const uint32_t* a,
                                         uint32_t b0, uint32_t b1) {
    asm volatile(
        "mma.sync.aligned.m16n8k16.row.col.f32.bf16.bf16.f32 "
        "{%0,%1,%2,%3}, {%4,%5,%6,%7}, {%8,%9}, {%0,%1,%2,%3};"
        : "+f"(d[0]), "+f"(d[1]), "+f"(d[2]), "+f"(d[3])
        : "r"(a[0]), "r"(a[1]), "r"(a[2]), "r"(a[3]), "r"(b0), "r"(b1));
}
// pack two fp32 -> bf16x2 (first arg in LOW half)
__device__ __forceinline__ uint32_t pack_bf16x2(float lo, float hi) {
    uint32_t d;
    asm("cvt.rn.bf16x2.f32 %0, %1, %2;" : "=r"(d) : "f"(hi), "f"(lo));
    return d;
}
#define CP_ASYNC16(dst, src) \
    asm volatile("cp.async.cg.shared.global [%0], [%1], 16;" \
                 :: "r"(dst), "l"(src) : "memory")
#define CP_COMMIT() asm volatile("cp.async.commit_group;" ::: "memory")
#define CP_WAIT1()  asm volatile("cp.async.wait_group 1;" ::: "memory")
#define CP_WAIT0()  asm volatile("cp.async.wait_group 0;" ::: "memory")

// ===========================================================================
// HMMA GEMM, bf16 3-term split, 512 threads (16 warps, 4x4), 3-stage cp.async
// BM=128, BN=128, BK=32. SMEM rows 80B -> conflict-free ldmatrix, no swizzle.
// ===========================================================================
#define G_BM 128
#define G_BN 128
#define G_BK 32
#define ROWB 80
static constexpr int TILE_B  = 128 * ROWB;      // 10240 B per tile
static constexpr int STAGE_B = 4 * TILE_B;      // AH|AL|BH|BL = 40960 B
static constexpr int GEMM_SMEM = 3 * STAGE_B;   // 122880 B

__global__ __launch_bounds__(512, 1)
void gemm_hmma_x3(const __nv_bfloat16* __restrict__ Ah,
                  const __nv_bfloat16* __restrict__ Al,
                  const __nv_bfloat16* __restrict__ Wh,
                  const __nv_bfloat16* __restrict__ Wl,
                  const float* __restrict__ bias,
                  const float* __restrict__ resid,
                  float* __restrict__ C,
                  int N, int K)
{
    extern __shared__ __align__(16) unsigned char dsm[];
    const uint32_t sb = smem_u32(dsm);

    const int tid  = threadIdx.x;
    const int wid  = tid >> 5, lane = tid & 31;
    const int wm   = wid & 3;          // warp m-block (32 rows)
    const int wn   = wid >> 2;         // warp n-block (32 cols)
    const int m0   = blockIdx.y * G_BM;
    const int n0   = blockIdx.x * G_BN;

    const uint32_t frag_off = (uint32_t)((lane & 15) * ROWB + (lane >> 4) * 16);

    float acc[2][4][4];
    #pragma unroll
    for (int i = 0; i < 2; i++)
        #pragma unroll
        for (int j = 0; j < 4; j++)
            #pragma unroll
            for (int q = 0; q < 4; q++) acc[i][j][q] = 0.f;

    // loader: 512 threads, 4 x 16B cp.async each (one per tile plane)
    const int lrow = tid >> 2;          // 0..127
    const int lc16 = tid & 3;           // 16B chunk within 64B data row
    const uint32_t doff = (uint32_t)(lrow * ROWB + lc16 * 16);

    auto issue = [&](int it, int stg) {
        const int k0 = it * G_BK;
        const uint32_t st = sb + stg * STAGE_B;
        size_t ao = (size_t)(m0 + lrow) * K + k0 + lc16 * 8;
        size_t bo = (size_t)(n0 + lrow) * K + k0 + lc16 * 8;
        CP_ASYNC16(st + 0 * TILE_B + doff, Ah + ao);
        CP_ASYNC16(st + 1 * TILE_B + doff, Al + ao);
        CP_ASYNC16(st + 2 * TILE_B + doff, Wh + bo);
        CP_ASYNC16(st + 3 * TILE_B + doff, Wl + bo);
    };

    const int KC = K / G_BK;
    issue(0, 0); CP_COMMIT();
    issue(1, 1); CP_COMMIT();

    int s_rd = 0, s_wr = 2;
    for (int it = 0; it < KC; it++) {
        if (it + 1 < KC) CP_WAIT1(); else CP_WAIT0();
        __syncthreads();                       // stage s_rd visible to all

        if (it + 2 < KC) { issue(it + 2, s_wr); CP_COMMIT(); }

        const uint32_t st = sb + s_rd * STAGE_B;
        #pragma unroll
        for (int kc = 0; kc < 2; kc++) {
            uint32_t ah[2][4], al[2][4], bh[2][4], bl[2][4];
            #pragma unroll
            for (int mi = 0; mi < 2; mi++) {
                uint32_t base = (uint32_t)((wm * 32 + mi * 16) * ROWB + kc * 32) + frag_off;
                ldsm_x4(ah[mi], st + 0 * TILE_B + base);
                ldsm_x4(al[mi], st + 1 * TILE_B + base);
            }
            #pragma unroll
            for (int nj = 0; nj < 2; nj++) {
                uint32_t base = (uint32_t)((wn * 32 + nj * 16) * ROWB + kc * 32) + frag_off;
                ldsm_x4(bh[nj], st + 2 * TILE_B + base);
                ldsm_x4(bl[nj], st + 3 * TILE_B + base);
            }
            // term-outermost: same-acc reuse distance = 8 MMAs
            #pragma unroll
            for (int mi = 0; mi < 2; mi++)
                #pragma unroll
                for (int nj = 0; nj < 2; nj++)
                    #pragma unroll
                    for (int h = 0; h < 2; h++)
                        mma_bf16(acc[mi][nj * 2 + h], ah[mi], bh[nj][h], bh[nj][h + 2]);
            #pragma unroll
            for (int mi = 0; mi < 2; mi++)
                #pragma unroll
                for (int nj = 0; nj < 2; nj++)
                    #pragma unroll
                    for (int h = 0; h < 2; h++)
                        mma_bf16(acc[mi][nj * 2 + h], al[mi], bh[nj][h], bh[nj][h + 2]);
            #pragma unroll
            for (int mi = 0; mi < 2; mi++)
                #pragma unroll
                for (int nj = 0; nj < 2; nj++)
                    #pragma unroll
                    for (int h = 0; h < 2; h++)
                        mma_bf16(acc[mi][nj * 2 + h], ah[mi], bl[nj][h], bl[nj][h + 2]);
        }
        s_rd = (s_rd + 1 == 3) ? 0 : s_rd + 1;
        s_wr = (s_wr + 1 == 3) ? 0 : s_wr + 1;
    }

    // ---- epilogue ----
    const int lg = lane >> 2;
    const int lq = lane & 3;
    #pragma unroll
    for (int mi = 0; mi < 2; mi++) {
        const int mbase = m0 + wm * 32 + mi * 16 + lg;
        #pragma unroll
        for (int ni = 0; ni < 4; ni++) {
            const int n = n0 + wn * 32 + ni * 8 + lq * 2;
            float2 bv = *(const float2*)(bias + n);
            float* a = acc[mi][ni];
            float2 o0 = make_float2(a[0] + bv.x, a[1] + bv.y);
            float2 o1 = make_float2(a[2] + bv.x, a[3] + bv.y);
            if (resid) {
                float2 r0 = *(const float2*)(resid + (size_t)mbase * N + n);
                float2 r1 = *(const float2*)(resid + (size_t)(mbase + 8) * N + n);
                o0.x += r0.x; o0.y += r0.y;
                o1.x += r1.x; o1.y += r1.y;
            }
            *(float2*)(C + (size_t)mbase * N + n)       = o0;
            *(float2*)(C + (size_t)(mbase + 8) * N + n) = o1;
        }
    }
}

// ---------------------------------------------------------------------------
// Weight hi/lo split
// ---------------------------------------------------------------------------
__global__ void wsplit_k(const float* __restrict__ w,
                         __nv_bfloat16* __restrict__ wh,
                         __nv_bfloat16* __restrict__ wl, int n4)
{
    int i = blockIdx.x * blockDim.x + threadIdx.x;
    if (i < n4) {
        float4 v = *(const float4*)(w + (size_t)i * 4);
        uint32_t h01 = pack_bf16x2(v.x, v.y), h23 = pack_bf16x2(v.z, v.w);
        float r0 = v.x - __uint_as_float(h01 << 16);
        float r1 = v.y - __uint_as_float(h01 & 0xFFFF0000u);
        float r2 = v.z - __uint_as_float(h23 << 16);
        float r3 = v.w - __uint_as_float(h23 & 0xFFFF0000u);
        *(uint2*)(wh + (size_t)i * 4) = make_uint2(h01, h23);
        *(uint2*)(wl + (size_t)i * 4) = make_uint2(pack_bf16x2(r0, r1), pack_bf16x2(r2, r3));
    }
}

// ---------------------------------------------------------------------------
// wbar[c] = (1/16) * sum_s xproj_w[17+s, c]
// ---------------------------------------------------------------------------
__global__ void compute_wbar_k(const float* __restrict__ xproj_w)
{
    int c = blockIdx.x * blockDim.x + threadIdx.x;
    if (c < DI) {
        float s = 0.f;
        #pragma unroll
        for (int k = 0; k < 16; k++)
            s += xproj_w[(size_t)(17 + k) * DI + c];
        g_wbar[c] = s * (1.f / 16.f);
    }
}

// ---------------------------------------------------------------------------
// LayerNorm -> bf16 hi/lo planes
// ---------------------------------------------------------------------------
__global__ void layernorm_k(const float* __restrict__ x,
                            const float* __restrict__ w,
                            const float* __restrict__ b)
{
    __shared__ float2 red[256];
    size_t row = blockIdx.x;
    int tid = threadIdx.x;

    const float4* xr = (const float4*)(x + row * DM);
    float4 v = xr[tid];
    float s  = v.x + v.y + v.z + v.w;
    float ss = v.x * v.x + v.y * v.y + v.z * v.z + v.w * v.w;
    red[tid] = make_float2(s, ss);
    __syncthreads();
    #pragma unroll
    for (int off = 128; off >= 1; off >>= 1) {
        if (tid < off) {
            red[tid].x += red[tid + off].x;
            red[tid].y += red[tid + off].y;
        }
        __syncthreads();
    }
    float mu  = red[0].x * (1.f / DM);
    float var = red[0].y * (1.f / DM) - mu * mu;
    float rstd = rsqrtf(var + 1e-5f);

    int c = tid * 4;
    const float4 wv = *(const float4*)(w + c);
    const float4 bv = *(const float4*)(b + c);
    float4 o;
    o.x = (v.x - mu) * rstd * wv.x + bv.x;
    o.y = (v.y - mu) * rstd * wv.y + bv.y;
    o.z = (v.z - mu) * rstd * wv.z + bv.z;
    o.w = (v.w - mu) * rstd * wv.w + bv.w;

    uint32_t h01 = pack_bf16x2(o.x, o.y), h23 = pack_bf16x2(o.z, o.w);
    float r0 = o.x - __uint_as_float(h01 << 16);
    float r1 = o.y - __uint_as_float(h01 & 0xFFFF0000u);
    float r2 = o.z - __uint_as_float(h23 << 16);
    float r3 = o.w - __uint_as_float(h23 & 0xFFFF0000u);
    *(uint2*)(g_xn_h + row * DM + c) = make_uint2(h01, h23);
    *(uint2*)(g_xn_l + row * DM + c) = make_uint2(pack_bf16x2(r0, r1), pack_bf16x2(r2, r3));
}

// ---------------------------------------------------------------------------
// Fused mid: conv(4) + SiLU + gate + z-gate -> bf16 hi/lo planes of y
// ---------------------------------------------------------------------------
#define TT 32

__global__ __launch_bounds__(256)
void fused_mid_k(const float* __restrict__ conv_w,
                 const float* __restrict__ conv_b,
                 const float* __restrict__ Dp)
{
    __shared__ float red[8];
    __shared__ float gate_sh;
    const int b   = blockIdx.y;
    const int t0  = blockIdx.x * TT;
    const int tid = threadIdx.x;
    const int lane = tid & 31, wrp = tid >> 5;
    const int c0 = tid * 8;

    float cw0[8], cw1[8], cw2[8], cw3[8], cb[8], wb[8], dd[8];
    #pragma unroll
    for (int i = 0; i < 8; i++) {
        float4 q = *(const float4*)(conv_w + (size_t)(c0 + i) * 4);
        cw0[i] = q.x; cw1[i] = q.y; cw2[i] = q.z; cw3[i] = q.w;
        cb[i] = conv_b[c0 + i];
        wb[i] = g_wbar[c0 + i];
        dd[i] = Dp[c0 + i];
    }

    float w0[8], w1[8], w2[8];
    #pragma unroll
    for (int j = 0; j < 3; j++) {
        int t = t0 - 3 + j;
        float* dst = (j == 0) ? w0 : (j == 1) ? w1 : w2;
        if (t >= 0) {
            const float* src = g_xz + ((size_t)b * TD + t) * (2 * DI) + c0;
            float4 a = *(const float4*)src;
            float4 c = *(const float4*)(src + 4);
            dst[0]=a.x; dst[1]=a.y; dst[2]=a.z; dst[3]=a.w;
            dst[4]=c.x; dst[5]=c.y; dst[6]=c.z; dst[7]=c.w;
        } else {
            #pragma unroll
            for (int i = 0; i < 8; i++) dst[i] = 0.f;
        }
    }

    for (int tt = 0; tt < TT; tt++) {
        const int t = t0 + tt;
        const size_t rb = ((size_t)b * TD + t) * (2 * DI);

        float cur[8];
        {
            const float* src = g_xz + rb + c0;
            float4 a = *(const float4*)src;
            float4 c = *(const float4*)(src + 4);
            cur[0]=a.x; cur[1]=a.y; cur[2]=a.z; cur[3]=a.w;
            cur[4]=c.x; cur[5]=c.y; cur[6]=c.z; cur[7]=c.w;
        }

        float xc[8], partial = 0.f;
        #pragma unroll
        for (int i = 0; i < 8; i++) {
            float a = cb[i] + w0[i]*cw0[i] + w1[i]*cw1[i] + w2[i]*cw2[i] + cur[i]*cw3[i];
            float sg = 1.f / (1.f + __expf(-a));
            xc[i] = a * sg;
            partial += xc[i] * wb[i];
        }

        #pragma unroll
        for (int off = 16; off >= 1; off >>= 1)
            partial += __shfl_xor_sync(0xffffffffu, partial, off);
        if (lane == 0) red[wrp] = partial;
        __syncthreads();
        if (tid == 0) {
            float s = 0.f;
            #pragma unroll
            for (int k = 0; k < 8; k++) s += red[k];
            gate_sh = 1.f / (1.f + __expf(-s));
        }
        __syncthreads();
        const float gate = gate_sh;

        float zv[8];
        {
            const float* src = g_xz + rb + DI + c0;
            float4 a = *(const float4*)src;
            float4 c = *(const float4*)(src + 4);
            zv[0]=a.x; zv[1]=a.y; zv[2]=a.z; zv[3]=a.w;
            zv[4]=c.x; zv[5]=c.y; zv[6]=c.z; zv[7]=c.w;
        }
        float out[8];
        #pragma unroll
        for (int i = 0; i < 8; i++) {
            float sz = zv[i] / (1.f + __expf(-zv[i]));
            out[i] = xc[i] * (gate + dd[i]) * sz;
        }

        uint32_t h[4], l[4];
        #pragma unroll
        for (int q = 0; q < 4; q++) {
            h[q] = pack_bf16x2(out[2 * q], out[2 * q + 1]);
            float ra = out[2 * q]      - __uint_as_float(h[q] << 16);
            float rbq = out[2 * q + 1] - __uint_as_float(h[q] & 0xFFFF0000u);
            l[q] = pack_bf16x2(ra, rbq);
        }
        size_t yo = ((size_t)b * TD + t) * DI + c0;
        *(uint4*)(g_y_h + yo) = make_uint4(h[0], h[1], h[2], h[3]);
        *(uint4*)(g_y_l + yo) = make_uint4(l[0], l[1], l[2], l[3]);

        #pragma unroll
        for (int i = 0; i < 8; i++) { w0[i] = w1[i]; w1[i] = w2[i]; w2[i] = cur[i]; }
    }
}

// ---------------------------------------------------------------------------
extern "C" void kernel_launch(void* const* d_in, const int* in_sizes, int n_in,
                              void* d_out, int out_size)
{
    const float* x       = (const float*)d_in[0];
    const float* norm_w  = (const float*)d_in[1];
    const float* norm_b  = (const float*)d_in[2];
    const float* in_w    = (const float*)d_in[3];
    const float* in_b    = (const float*)d_in[4];
    const float* conv_w  = (const float*)d_in[5];
    const float* conv_b  = (const float*)d_in[6];
    const float* xproj_w = (const float*)d_in[7];
    const float* Dp      = (const float*)d_in[9];
    const float* out_w   = (const float*)d_in[10];
    const float* out_b   = (const float*)d_in[11];
    float* out = (float*)d_out;

    __nv_bfloat16 *xnh, *xnl, *yh, *yl, *w1h, *w1l, *w2h, *w2l;
    float *xz_p;
    cudaGetSymbolAddress((void**)&xnh, g_xn_h);
    cudaGetSymbolAddress((void**)&xnl, g_xn_l);
    cudaGetSymbolAddress((void**)&xz_p, g_xz);
    cudaGetSymbolAddress((void**)&yh, g_y_h);
    cudaGetSymbolAddress((void**)&yl, g_y_l);
    cudaGetSymbolAddress((void**)&w1h, g_w1h);
    cudaGetSymbolAddress((void**)&w1l, g_w1l);
    cudaGetSymbolAddress((void**)&w2h, g_w2h);
    cudaGetSymbolAddress((void**)&w2l, g_w2l);

    static int smem_set = 0;
    if (!smem_set) {
        cudaFuncSetAttribute(gemm_hmma_x3,
                             cudaFuncAttributeMaxDynamicSharedMemorySize, GEMM_SMEM);
        smem_set = 1;
    }

    // weight splits (elementwise, tiny)
    {
        int n4a = (2 * DI) * DM / 4;
        wsplit_k<<<(n4a + 255) / 256, 256>>>(in_w, w1h, w1l, n4a);
        int n4b = DM * DI / 4;
        wsplit_k<<<(n4b + 255) / 256, 256>>>(out_w, w2h, w2l, n4b);
    }
    compute_wbar_k<<<(DI + 255) / 256, 256>>>(xproj_w);
    layernorm_k<<<(int)MROWS, 256>>>(x, norm_w, norm_b);

    // GEMM1: xz = xn @ in_w.T + in_b   (M=16384, N=4096, K=1024)
    gemm_hmma_x3<<<dim3((2 * DI) / G_BN, (int)MROWS / G_BM), 512, GEMM_SMEM>>>(
        xnh, xnl, w1h, w1l, in_b, nullptr, xz_p, 2 * DI, DM);

    // conv + silu + gate + z-gate -> y planes
    fused_mid_k<<<dim3(TD / TT, BD), 256>>>(conv_w, conv_b, Dp);

    // GEMM2: out = y @ out_w.T + out_b + x   (M=16384, N=1024, K=2048)
    gemm_hmma_x3<<<dim3(DM / G_BN, (int)MROWS / G_BM), 512, GEMM_SMEM>>>(
        yh, yl, w2h, w2l, out_b, x, out, DM, DI);
}

// round 10
// speedup vs baseline: 4.0772x; 2.0205x over previous
#include <cuda_runtime.h>
#include <cuda_fp16.h>
#include <math.h>
#include <stdint.h>

// Problem constants
static constexpr int  BD = 4;
static constexpr int  TD = 4096;
static constexpr int  DM = 1024;           // d_model
static constexpr int  DI = 2048;           // d_inner
static constexpr size_t MROWS = (size_t)BD * TD;   // 16384

// Scratch (fp16 single-plane operands)
__device__ __half g_xn[MROWS * DM];
__device__ float  g_xz[MROWS * 2 * DI];
__device__ __half g_y [MROWS * DI];
__device__ __half g_w1[(size_t)(2 * DI) * DM];
__device__ __half g_w2[(size_t)DM * DI];
__device__ float  g_wbar[DI];

// ===========================================================================
// PTX helpers (sm_80-class — valid at base sm_103 target)
// ===========================================================================
__device__ __forceinline__ uint32_t smem_u32(const void* p) {
    uint32_t a;
    asm("{ .reg .u64 t; cvta.to.shared.u64 t, %1; cvt.u32.u64 %0, t; }"
        : "=r"(a) : "l"(p));
    return a;
}
__device__ __forceinline__ void ldsm_x4(uint32_t* r, uint32_t addr) {
    asm volatile("ldmatrix.sync.aligned.m8n8.x4.shared.b16 {%0,%1,%2,%3}, [%4];"
                 : "=r"(r[0]), "=r"(r[1]), "=r"(r[2]), "=r"(r[3]) : "r"(addr));
}
__device__ __forceinline__ void mma_fp16(float* d, const uint32_t* a,
                                         uint32_t b0, uint32_t b1) {
    asm volatile(
        "mma.sync.aligned.m16n8k16.row.col.f32.f16.f16.f32 "
        "{%0,%1,%2,%3}, {%4,%5,%6,%7}, {%8,%9}, {%0,%1,%2,%3};"
        : "+f"(d[0]), "+f"(d[1]), "+f"(d[2]), "+f"(d[3])
        : "r"(a[0]), "r"(a[1]), "r"(a[2]), "r"(a[3]), "r"(b0), "r"(b1));
}
__device__ __forceinline__ uint32_t pack_h2(float a, float b) {
    __half2 h = __floats2half2_rn(a, b);   // a -> low half
    return *(uint32_t*)&h;
}
#define CP_ASYNC16(dst, src) \
    asm volatile("cp.async.cg.shared.global [%0], [%1], 16;" \
                 :: "r"(dst), "l"(src) : "memory")
#define CP_COMMIT() asm volatile("cp.async.commit_group;" ::: "memory")
#define CP_WAIT1()  asm volatile("cp.async.wait_group 1;" ::: "memory")
#define CP_WAIT0()  asm volatile("cp.async.wait_group 0;" ::: "memory")

// ===========================================================================
// fp16 single-term HMMA GEMM: C = A @ W^T + bias (+ resid)
// BM=128, BN=128, BK=32; 512 threads (16 warps, 4x4); 3-stage cp.async.
// SMEM rows 80B (64B data + 16B pad) -> conflict-free ldmatrix, no swizzle.
// ===========================================================================
#define G_BM 128
#define G_BN 128
#define G_BK 32
#define ROWB 80
static constexpr int TILE_B  = 128 * ROWB;      // 10240 B per tile
static constexpr int STAGE_B = 2 * TILE_B;      // A | B = 20480 B
static constexpr int GEMM_SMEM = 3 * STAGE_B;   // 61440 B

__global__ __launch_bounds__(512, 1)
void gemm_hmma_f16(const __half* __restrict__ Ah,
                   const __half* __restrict__ Wh,
                   const float* __restrict__ bias,
                   const float* __restrict__ resid,
                   float* __restrict__ C,
                   int N, int K)
{
    extern __shared__ __align__(16) unsigned char dsm[];
    const uint32_t sb = smem_u32(dsm);

    const int tid  = threadIdx.x;
    const int wid  = tid >> 5, lane = tid & 31;
    const int wm   = wid & 3;          // warp m-block (32 rows)
    const int wn   = wid >> 2;         // warp n-block (32 cols)
    const int m0   = blockIdx.y * G_BM;
    const int n0   = blockIdx.x * G_BN;

    const uint32_t frag_off = (uint32_t)((lane & 15) * ROWB + (lane >> 4) * 16);

    float acc[2][4][4];
    #pragma unroll
    for (int i = 0; i < 2; i++)
        #pragma unroll
        for (int j = 0; j < 4; j++)
            #pragma unroll
            for (int q = 0; q < 4; q++) acc[i][j][q] = 0.f;

    // loader: 512 threads, 1 x 16B cp.async per tile each
    const int lrow = tid >> 2;          // 0..127
    const int lc16 = tid & 3;           // 16B chunk within 64B data row
    const uint32_t doff = (uint32_t)(lrow * ROWB + lc16 * 16);

    auto issue = [&](int it, int stg) {
        const int k0 = it * G_BK;
        const uint32_t st = sb + stg * STAGE_B;
        size_t ao = (size_t)(m0 + lrow) * K + k0 + lc16 * 8;
        size_t bo = (size_t)(n0 + lrow) * K + k0 + lc16 * 8;
        CP_ASYNC16(st + 0 * TILE_B + doff, Ah + ao);
        CP_ASYNC16(st + 1 * TILE_B + doff, Wh + bo);
    };

    const int KC = K / G_BK;
    issue(0, 0); CP_COMMIT();
    issue(1, 1); CP_COMMIT();

    int s_rd = 0, s_wr = 2;
    for (int it = 0; it < KC; it++) {
        if (it + 1 < KC) CP_WAIT1(); else CP_WAIT0();
        __syncthreads();                       // stage s_rd visible to all

        if (it + 2 < KC) { issue(it + 2, s_wr); CP_COMMIT(); }

        const uint32_t st = sb + s_rd * STAGE_B;
        #pragma unroll
        for (int kc = 0; kc < 2; kc++) {
            uint32_t a[2][4], b[2][4];
            #pragma unroll
            for (int mi = 0; mi < 2; mi++) {
                uint32_t base = (uint32_t)((wm * 32 + mi * 16) * ROWB + kc * 32) + frag_off;
                ldsm_x4(a[mi], st + 0 * TILE_B + base);
            }
            #pragma unroll
            for (int nj = 0; nj < 2; nj++) {
                uint32_t base = (uint32_t)((wn * 32 + nj * 16) * ROWB + kc * 32) + frag_off;
                ldsm_x4(b[nj], st + 1 * TILE_B + base);
            }
            #pragma unroll
            for (int mi = 0; mi < 2; mi++)
                #pragma unroll
                for (int nj = 0; nj < 2; nj++)
                    #pragma unroll
                    for (int h = 0; h < 2; h++)
                        mma_fp16(acc[mi][nj * 2 + h], a[mi], b[nj][h], b[nj][h + 2]);
        }
        s_rd = (s_rd + 1 == 3) ? 0 : s_rd + 1;
        s_wr = (s_wr + 1 == 3) ? 0 : s_wr + 1;
    }

    // ---- epilogue ----
    const int lg = lane >> 2;
    const int lq = lane & 3;
    #pragma unroll
    for (int mi = 0; mi < 2; mi++) {
        const int mbase = m0 + wm * 32 + mi * 16 + lg;
        #pragma unroll
        for (int ni = 0; ni < 4; ni++) {
            const int n = n0 + wn * 32 + ni * 8 + lq * 2;
            float2 bv = *(const float2*)(bias + n);
            float* a = acc[mi][ni];
            float2 o0 = make_float2(a[0] + bv.x, a[1] + bv.y);
            float2 o1 = make_float2(a[2] + bv.x, a[3] + bv.y);
            if (resid) {
                float2 r0 = *(const float2*)(resid + (size_t)mbase * N + n);
                float2 r1 = *(const float2*)(resid + (size_t)(mbase + 8) * N + n);
                o0.x += r0.x; o0.y += r0.y;
                o1.x += r1.x; o1.y += r1.y;
            }
            *(float2*)(C + (size_t)mbase * N + n)       = o0;
            *(float2*)(C + (size_t)(mbase + 8) * N + n) = o1;
        }
    }
}

// ---------------------------------------------------------------------------
// Weight fp32 -> fp16 convert
// ---------------------------------------------------------------------------
__global__ void wconv_k(const float* __restrict__ w,
                        __half* __restrict__ wh, int n4)
{
    int i = blockIdx.x * blockDim.x + threadIdx.x;
    if (i < n4) {
        float4 v = *(const float4*)(w + (size_t)i * 4);
        *(uint2*)(wh + (size_t)i * 4) =
            make_uint2(pack_h2(v.x, v.y), pack_h2(v.z, v.w));
    }
}

// ---------------------------------------------------------------------------
// wbar[c] = (1/16) * sum_s xproj_w[17+s, c]
// ---------------------------------------------------------------------------
__global__ void compute_wbar_k(const float* __restrict__ xproj_w)
{
    int c = blockIdx.x * blockDim.x + threadIdx.x;
    if (c < DI) {
        float s = 0.f;
        #pragma unroll
        for (int k = 0; k < 16; k++)
            s += xproj_w[(size_t)(17 + k) * DI + c];
        g_wbar[c] = s * (1.f / 16.f);
    }
}

// ---------------------------------------------------------------------------
// LayerNorm -> fp16 plane
// ---------------------------------------------------------------------------
__global__ void layernorm_k(const float* __restrict__ x,
                            const float* __restrict__ w,
                            const float* __restrict__ b)
{
    __shared__ float2 red[256];
    size_t row = blockIdx.x;
    int tid = threadIdx.x;

    const float4* xr = (const float4*)(x + row * DM);
    float4 v = xr[tid];
    float s  = v.x + v.y + v.z + v.w;
    float ss = v.x * v.x + v.y * v.y + v.z * v.z + v.w * v.w;
    red[tid] = make_float2(s, ss);
    __syncthreads();
    #pragma unroll
    for (int off = 128; off >= 1; off >>= 1) {
        if (tid < off) {
            red[tid].x += red[tid + off].x;
            red[tid].y += red[tid + off].y;
        }
        __syncthreads();
    }
    float mu  = red[0].x * (1.f / DM);
    float var = red[0].y * (1.f / DM) - mu * mu;
    float rstd = rsqrtf(var + 1e-5f);

    int c = tid * 4;
    const float4 wv = *(const float4*)(w + c);
    const float4 bv = *(const float4*)(b + c);
    float4 o;
    o.x = (v.x - mu) * rstd * wv.x + bv.x;
    o.y = (v.y - mu) * rstd * wv.y + bv.y;
    o.z = (v.z - mu) * rstd * wv.z + bv.z;
    o.w = (v.w - mu) * rstd * wv.w + bv.w;

    *(uint2*)(g_xn + row * DM + c) =
        make_uint2(pack_h2(o.x, o.y), pack_h2(o.z, o.w));
}

// ---------------------------------------------------------------------------
// Fused mid: conv(4) + SiLU + gate + z-gate -> fp16 plane of y
// ---------------------------------------------------------------------------
#define TT 32

__global__ __launch_bounds__(256)
void fused_mid_k(const float* __restrict__ conv_w,
                 const float* __restrict__ conv_b,
                 const float* __restrict__ Dp)
{
    __shared__ float red[8];
    __shared__ float gate_sh;
    const int b   = blockIdx.y;
    const int t0  = blockIdx.x * TT;
    const int tid = threadIdx.x;
    const int lane = tid & 31, wrp = tid >> 5;
    const int c0 = tid * 8;

    float cw0[8], cw1[8], cw2[8], cw3[8], cb[8], wb[8], dd[8];
    #pragma unroll
    for (int i = 0; i < 8; i++) {
        float4 q = *(const float4*)(conv_w + (size_t)(c0 + i) * 4);
        cw0[i] = q.x; cw1[i] = q.y; cw2[i] = q.z; cw3[i] = q.w;
        cb[i] = conv_b[c0 + i];
        wb[i] = g_wbar[c0 + i];
        dd[i] = Dp[c0 + i];
    }

    float w0[8], w1[8], w2[8];
    #pragma unroll
    for (int j = 0; j < 3; j++) {
        int t = t0 - 3 + j;
        float* dst = (j == 0) ? w0 : (j == 1) ? w1 : w2;
        if (t >= 0) {
            const float* src = g_xz + ((size_t)b * TD + t) * (2 * DI) + c0;
            float4 a = *(const float4*)src;
            float4 c = *(const float4*)(src + 4);
            dst[0]=a.x; dst[1]=a.y; dst[2]=a.z; dst[3]=a.w;
            dst[4]=c.x; dst[5]=c.y; dst[6]=c.z; dst[7]=c.w;
        } else {
            #pragma unroll
            for (int i = 0; i < 8; i++) dst[i] = 0.f;
        }
    }

    for (int tt = 0; tt < TT; tt++) {
        const int t = t0 + tt;
        const size_t rb = ((size_t)b * TD + t) * (2 * DI);

        float cur[8];
        {
            const float* src = g_xz + rb + c0;
            float4 a = *(const float4*)src;
            float4 c = *(const float4*)(src + 4);
            cur[0]=a.x; cur[1]=a.y; cur[2]=a.z; cur[3]=a.w;
            cur[4]=c.x; cur[5]=c.y; cur[6]=c.z; cur[7]=c.w;
        }

        float xc[8], partial = 0.f;
        #pragma unroll
        for (int i = 0; i < 8; i++) {
            float a = cb[i] + w0[i]*cw0[i] + w1[i]*cw1[i] + w2[i]*cw2[i] + cur[i]*cw3[i];
            float sg = 1.f / (1.f + __expf(-a));
            xc[i] = a * sg;
            partial += xc[i] * wb[i];
        }

        #pragma unroll
        for (int off = 16; off >= 1; off >>= 1)
            partial += __shfl_xor_sync(0xffffffffu, partial, off);
        if (lane == 0) red[wrp] = partial;
        __syncthreads();
        if (tid == 0) {
            float s = 0.f;
            #pragma unroll
            for (int k = 0; k < 8; k++) s += red[k];
            gate_sh = 1.f / (1.f + __expf(-s));
        }
        __syncthreads();
        const float gate = gate_sh;

        float zv[8];
        {
            const float* src = g_xz + rb + DI + c0;
            float4 a = *(const float4*)src;
            float4 c = *(const float4*)(src + 4);
            zv[0]=a.x; zv[1]=a.y; zv[2]=a.z; zv[3]=a.w;
            zv[4]=c.x; zv[5]=c.y; zv[6]=c.z; zv[7]=c.w;
        }
        float out[8];
        #pragma unroll
        for (int i = 0; i < 8; i++) {
            float sz = zv[i] / (1.f + __expf(-zv[i]));
            out[i] = xc[i] * (gate + dd[i]) * sz;
        }

        size_t yo = ((size_t)b * TD + t) * DI + c0;
        *(uint4*)(g_y + yo) = make_uint4(
            pack_h2(out[0], out[1]), pack_h2(out[2], out[3]),
            pack_h2(out[4], out[5]), pack_h2(out[6], out[7]));

        #pragma unroll
        for (int i = 0; i < 8; i++) { w0[i] = w1[i]; w1[i] = w2[i]; w2[i] = cur[i]; }
    }
}

// ---------------------------------------------------------------------------
extern "C" void kernel_launch(void* const* d_in, const int* in_sizes, int n_in,
                              void* d_out, int out_size)
{
    const float* x       = (const float*)d_in[0];
    const float* norm_w  = (const float*)d_in[1];
    const float* norm_b  = (const float*)d_in[2];
    const float* in_w    = (const float*)d_in[3];
    const float* in_b    = (const float*)d_in[4];
    const float* conv_w  = (const float*)d_in[5];
    const float* conv_b  = (const float*)d_in[6];
    const float* xproj_w = (const float*)d_in[7];
    const float* Dp      = (const float*)d_in[9];
    const float* out_w   = (const float*)d_in[10];
    const float* out_b   = (const float*)d_in[11];
    float* out = (float*)d_out;

    __half *xn_p, *y_p, *w1_p, *w2_p;
    float *xz_p;
    cudaGetSymbolAddress((void**)&xn_p, g_xn);
    cudaGetSymbolAddress((void**)&xz_p, g_xz);
    cudaGetSymbolAddress((void**)&y_p,  g_y);
    cudaGetSymbolAddress((void**)&w1_p, g_w1);
    cudaGetSymbolAddress((void**)&w2_p, g_w2);

    static int smem_set = 0;
    if (!smem_set) {
        cudaFuncSetAttribute(gemm_hmma_f16,
                             cudaFuncAttributeMaxDynamicSharedMemorySize, GEMM_SMEM);
        smem_set = 1;
    }

    // weight converts (elementwise, tiny)
    {
        int n4a = (2 * DI) * DM / 4;
        wconv_k<<<(n4a + 255) / 256, 256>>>(in_w, w1_p, n4a);
        int n4b = DM * DI / 4;
        wconv_k<<<(n4b + 255) / 256, 256>>>(out_w, w2_p, n4b);
    }
    compute_wbar_k<<<(DI + 255) / 256, 256>>>(xproj_w);
    layernorm_k<<<(int)MROWS, 256>>>(x, norm_w, norm_b);

    // GEMM1: xz = xn @ in_w.T + in_b   (M=16384, N=4096, K=1024)
    gemm_hmma_f16<<<dim3((2 * DI) / G_BN, (int)MROWS / G_BM), 512, GEMM_SMEM>>>(
        xn_p, w1_p, in_b, nullptr, xz_p, 2 * DI, DM);

    // conv + silu + gate + z-gate -> y (fp16)
    fused_mid_k<<<dim3(TD / TT, BD), 256>>>(conv_w, conv_b, Dp);

    // GEMM2: out = y @ out_w.T + out_b + x   (M=16384, N=1024, K=2048)
    gemm_hmma_f16<<<dim3(DM / G_BN, (int)MROWS / G_BM), 512, GEMM_SMEM>>>(
        y_p, w2_p, out_b, x, out, DM, DI);
}

// round 11
// speedup vs baseline: 4.7497x; 1.1649x over previous
#include <cuda_runtime.h>
#include <cuda_fp16.h>
#include <math.h>
#include <stdint.h>

// Problem constants
static constexpr int  BD = 4;
static constexpr int  TD = 4096;
static constexpr int  DM = 1024;           // d_model
static constexpr int  DI = 2048;           // d_inner
static constexpr size_t MROWS = (size_t)BD * TD;   // 16384

// Scratch (fp16 single-plane operands)
__device__ __half g_xn[MROWS * DM];
__device__ float  g_xz[MROWS * 2 * DI];
__device__ __half g_y [MROWS * DI];
__device__ __half g_w1[(size_t)(2 * DI) * DM];
__device__ __half g_w2[(size_t)DM * DI];
__device__ float  g_wbar[DI];

// ===========================================================================
// PTX helpers (sm_80-class — valid at base sm_103 target)
// ===========================================================================
__device__ __forceinline__ uint32_t smem_u32(const void* p) {
    uint32_t a;
    asm("{ .reg .u64 t; cvta.to.shared.u64 t, %1; cvt.u32.u64 %0, t; }"
        : "=r"(a) : "l"(p));
    return a;
}
__device__ __forceinline__ void ldsm_x4(uint32_t* r, uint32_t addr) {
    asm volatile("ldmatrix.sync.aligned.m8n8.x4.shared.b16 {%0,%1,%2,%3}, [%4];"
                 : "=r"(r[0]), "=r"(r[1]), "=r"(r[2]), "=r"(r[3]) : "r"(addr));
}
__device__ __forceinline__ void mma_fp16(float* d, const uint32_t* a,
                                         uint32_t b0, uint32_t b1) {
    asm volatile(
        "mma.sync.aligned.m16n8k16.row.col.f32.f16.f16.f32 "
        "{%0,%1,%2,%3}, {%4,%5,%6,%7}, {%8,%9}, {%0,%1,%2,%3};"
        : "+f"(d[0]), "+f"(d[1]), "+f"(d[2]), "+f"(d[3])
        : "r"(a[0]), "r"(a[1]), "r"(a[2]), "r"(a[3]), "r"(b0), "r"(b1));
}
__device__ __forceinline__ uint32_t pack_h2(float a, float b) {
    __half2 h = __floats2half2_rn(a, b);   // a -> low half
    return *(uint32_t*)&h;
}
#define CP_ASYNC16(dst, src) \
    asm volatile("cp.async.cg.shared.global [%0], [%1], 16;" \
                 :: "r"(dst), "l"(src) : "memory")
#define CP_COMMIT() asm volatile("cp.async.commit_group;" ::: "memory")
#define CP_WAIT1()  asm volatile("cp.async.wait_group 1;" ::: "memory")
#define CP_WAIT0()  asm volatile("cp.async.wait_group 0;" ::: "memory")

// ===========================================================================
// fp16 HMMA GEMM: C = A @ W^T + bias (+ resid)
// BM=128, BN=256, BK=64; 512 threads (16 warps, 4x4, warp tile 32x64);
// 3-stage cp.async. SMEM rows 144B (128B data + 16B pad) -> conflict-free
// ldmatrix (row stride = 36 banks -> 8-row group covers all banks).
// ===========================================================================
#define G_BM 128
#define G_BN 256
#define G_BK 64
#define ROWB 144
static constexpr int TILE_A  = 128 * ROWB;            // 18432 B
static constexpr int TILE_BB = 256 * ROWB;            // 36864 B
static constexpr int STAGE_B = TILE_A + TILE_BB;      // 55296 B
static constexpr int GEMM_SMEM = 3 * STAGE_B;         // 165888 B

__global__ __launch_bounds__(512, 1)
void gemm_hmma_f16(const __half* __restrict__ Ah,
                   const __half* __restrict__ Wh,
                   const float* __restrict__ bias,
                   const float* __restrict__ resid,
                   float* __restrict__ C,
                   int N, int K)
{
    extern __shared__ __align__(16) unsigned char dsm[];
    const uint32_t sb = smem_u32(dsm);

    const int tid  = threadIdx.x;
    const int wid  = tid >> 5, lane = tid & 31;
    const int wm   = wid & 3;          // warp m-block (32 rows)
    const int wn   = wid >> 2;         // warp n-block (64 cols)
    const int m0   = blockIdx.y * G_BM;
    const int n0   = blockIdx.x * G_BN;

    const uint32_t frag_off = (uint32_t)((lane & 15) * ROWB + (lane >> 4) * 16);

    float acc[2][8][4];
    #pragma unroll
    for (int i = 0; i < 2; i++)
        #pragma unroll
        for (int j = 0; j < 8; j++)
            #pragma unroll
            for (int q = 0; q < 4; q++) acc[i][j][q] = 0.f;

    // loader: BK=64 -> 8 x 16B chunks per row. A: 1024 chunks, B: 2048 chunks.
    auto issue = [&](int it, int stg) {
        const int k0 = it * G_BK;
        const uint32_t st = sb + stg * STAGE_B;
        #pragma unroll
        for (int j = 0; j < 2; j++) {          // A
            int idx = tid + j * 512;
            int row = idx >> 3, c16 = idx & 7;
            CP_ASYNC16(st + (uint32_t)(row * ROWB + c16 * 16),
                       Ah + (size_t)(m0 + row) * K + k0 + c16 * 8);
        }
        #pragma unroll
        for (int j = 0; j < 4; j++) {          // B
            int idx = tid + j * 512;
            int row = idx >> 3, c16 = idx & 7;
            CP_ASYNC16(st + TILE_A + (uint32_t)(row * ROWB + c16 * 16),
                       Wh + (size_t)(n0 + row) * K + k0 + c16 * 8);
        }
    };

    const int KC = K / G_BK;
    issue(0, 0); CP_COMMIT();
    issue(1, 1); CP_COMMIT();

    int s_rd = 0, s_wr = 2;
    for (int it = 0; it < KC; it++) {
        if (it + 1 < KC) CP_WAIT1(); else CP_WAIT0();
        __syncthreads();                       // stage s_rd visible to all

        if (it + 2 < KC) { issue(it + 2, s_wr); CP_COMMIT(); }

        const uint32_t st = sb + s_rd * STAGE_B;
        #pragma unroll
        for (int kc = 0; kc < 4; kc++) {
            uint32_t a[2][4], b[4][4];
            #pragma unroll
            for (int mi = 0; mi < 2; mi++) {
                uint32_t base = (uint32_t)((wm * 32 + mi * 16) * ROWB + kc * 32) + frag_off;
                ldsm_x4(a[mi], st + base);
            }
            #pragma unroll
            for (int nj = 0; nj < 4; nj++) {
                uint32_t base = (uint32_t)((wn * 64 + nj * 16) * ROWB + kc * 32) + frag_off;
                ldsm_x4(b[nj], st + TILE_A + base);
            }
            #pragma unroll
            for (int mi = 0; mi < 2; mi++)
                #pragma unroll
                for (int nj = 0; nj < 4; nj++)
                    #pragma unroll
                    for (int h = 0; h < 2; h++)
                        mma_fp16(acc[mi][nj * 2 + h], a[mi], b[nj][h], b[nj][h + 2]);
        }
        s_rd = (s_rd + 1 == 3) ? 0 : s_rd + 1;
        s_wr = (s_wr + 1 == 3) ? 0 : s_wr + 1;
    }

    // ---- epilogue ----
    const int lg = lane >> 2;
    const int lq = lane & 3;
    #pragma unroll
    for (int mi = 0; mi < 2; mi++) {
        const int mbase = m0 + wm * 32 + mi * 16 + lg;
        #pragma unroll
        for (int ni = 0; ni < 8; ni++) {
            const int n = n0 + wn * 64 + ni * 8 + lq * 2;
            float2 bv = *(const float2*)(bias + n);
            float* a = acc[mi][ni];
            float2 o0 = make_float2(a[0] + bv.x, a[1] + bv.y);
            float2 o1 = make_float2(a[2] + bv.x, a[3] + bv.y);
            if (resid) {
                float2 r0 = *(const float2*)(resid + (size_t)mbase * N + n);
                float2 r1 = *(const float2*)(resid + (size_t)(mbase + 8) * N + n);
                o0.x += r0.x; o0.y += r0.y;
                o1.x += r1.x; o1.y += r1.y;
            }
            *(float2*)(C + (size_t)mbase * N + n)       = o0;
            *(float2*)(C + (size_t)(mbase + 8) * N + n) = o1;
        }
    }
}

// ---------------------------------------------------------------------------
// Weight fp32 -> fp16 convert
// ---------------------------------------------------------------------------
__global__ void wconv_k(const float* __restrict__ w,
                        __half* __restrict__ wh, int n4)
{
    int i = blockIdx.x * blockDim.x + threadIdx.x;
    if (i < n4) {
        float4 v = *(const float4*)(w + (size_t)i * 4);
        *(uint2*)(wh + (size_t)i * 4) =
            make_uint2(pack_h2(v.x, v.y), pack_h2(v.z, v.w));
    }
}

// ---------------------------------------------------------------------------
// wbar[c] = (1/16) * sum_s xproj_w[17+s, c]
// ---------------------------------------------------------------------------
__global__ void compute_wbar_k(const float* __restrict__ xproj_w)
{
    int c = blockIdx.x * blockDim.x + threadIdx.x;
    if (c < DI) {
        float s = 0.f;
        #pragma unroll
        for (int k = 0; k < 16; k++)
            s += xproj_w[(size_t)(17 + k) * DI + c];
        g_wbar[c] = s * (1.f / 16.f);
    }
}

// ---------------------------------------------------------------------------
// LayerNorm -> fp16 plane
// ---------------------------------------------------------------------------
__global__ void layernorm_k(const float* __restrict__ x,
                            const float* __restrict__ w,
                            const float* __restrict__ b)
{
    __shared__ float2 red[256];
    size_t row = blockIdx.x;
    int tid = threadIdx.x;

    const float4* xr = (const float4*)(x + row * DM);
    float4 v = xr[tid];
    float s  = v.x + v.y + v.z + v.w;
    float ss = v.x * v.x + v.y * v.y + v.z * v.z + v.w * v.w;
    red[tid] = make_float2(s, ss);
    __syncthreads();
    #pragma unroll
    for (int off = 128; off >= 1; off >>= 1) {
        if (tid < off) {
            red[tid].x += red[tid + off].x;
            red[tid].y += red[tid + off].y;
        }
        __syncthreads();
    }
    float mu  = red[0].x * (1.f / DM);
    float var = red[0].y * (1.f / DM) - mu * mu;
    float rstd = rsqrtf(var + 1e-5f);

    int c = tid * 4;
    const float4 wv = *(const float4*)(w + c);
    const float4 bv = *(const float4*)(b + c);
    float4 o;
    o.x = (v.x - mu) * rstd * wv.x + bv.x;
    o.y = (v.y - mu) * rstd * wv.y + bv.y;
    o.z = (v.z - mu) * rstd * wv.z + bv.z;
    o.w = (v.w - mu) * rstd * wv.w + bv.w;

    *(uint2*)(g_xn + row * DM + c) =
        make_uint2(pack_h2(o.x, o.y), pack_h2(o.z, o.w));
}

// ---------------------------------------------------------------------------
// Fused mid: conv(4) + SiLU + gate + z-gate -> fp16 plane of y
// ---------------------------------------------------------------------------
#define TT 16

__global__ __launch_bounds__(256)
void fused_mid_k(const float* __restrict__ conv_w,
                 const float* __restrict__ conv_b,
                 const float* __restrict__ Dp)
{
    __shared__ float red[8];
    __shared__ float gate_sh;
    const int b   = blockIdx.y;
    const int t0  = blockIdx.x * TT;
    const int tid = threadIdx.x;
    const int lane = tid & 31, wrp = tid >> 5;
    const int c0 = tid * 8;

    float cw0[8], cw1[8], cw2[8], cw3[8], cb[8], wb[8], dd[8];
    #pragma unroll
    for (int i = 0; i < 8; i++) {
        float4 q = *(const float4*)(conv_w + (size_t)(c0 + i) * 4);
        cw0[i] = q.x; cw1[i] = q.y; cw2[i] = q.z; cw3[i] = q.w;
        cb[i] = conv_b[c0 + i];
        wb[i] = g_wbar[c0 + i];
        dd[i] = Dp[c0 + i];
    }

    float w0[8], w1[8], w2[8];
    #pragma unroll
    for (int j = 0; j < 3; j++) {
        int t = t0 - 3 + j;
        float* dst = (j == 0) ? w0 : (j == 1) ? w1 : w2;
        if (t >= 0) {
            const float* src = g_xz + ((size_t)b * TD + t) * (2 * DI) + c0;
            float4 a = *(const float4*)src;
            float4 c = *(const float4*)(src + 4);
            dst[0]=a.x; dst[1]=a.y; dst[2]=a.z; dst[3]=a.w;
            dst[4]=c.x; dst[5]=c.y; dst[6]=c.z; dst[7]=c.w;
        } else {
            #pragma unroll
            for (int i = 0; i < 8; i++) dst[i] = 0.f;
        }
    }

    for (int tt = 0; tt < TT; tt++) {
        const int t = t0 + tt;
        const size_t rb = ((size_t)b * TD + t) * (2 * DI);

        float cur[8];
        {
            const float* src = g_xz + rb + c0;
            float4 a = *(const float4*)src;
            float4 c = *(const float4*)(src + 4);
            cur[0]=a.x; cur[1]=a.y; cur[2]=a.z; cur[3]=a.w;
            cur[4]=c.x; cur[5]=c.y; cur[6]=c.z; cur[7]=c.w;
        }

        float xc[8], partial = 0.f;
        #pragma unroll
        for (int i = 0; i < 8; i++) {
            float a = cb[i] + w0[i]*cw0[i] + w1[i]*cw1[i] + w2[i]*cw2[i] + cur[i]*cw3[i];
            float sg = 1.f / (1.f + __expf(-a));
            xc[i] = a * sg;
            partial += xc[i] * wb[i];
        }

        #pragma unroll
        for (int off = 16; off >= 1; off >>= 1)
            partial += __shfl_xor_sync(0xffffffffu, partial, off);
        if (lane == 0) red[wrp] = partial;
        __syncthreads();
        if (tid == 0) {
            float s = 0.f;
            #pragma unroll
            for (int k = 0; k < 8; k++) s += red[k];
            gate_sh = 1.f / (1.f + __expf(-s));
        }
        __syncthreads();
        const float gate = gate_sh;

        float zv[8];
        {
            const float* src = g_xz + rb + DI + c0;
            float4 a = *(const float4*)src;
            float4 c = *(const float4*)(src + 4);
            zv[0]=a.x; zv[1]=a.y; zv[2]=a.z; zv[3]=a.w;
            zv[4]=c.x; zv[5]=c.y; zv[6]=c.z; zv[7]=c.w;
        }
        float out[8];
        #pragma unroll
        for (int i = 0; i < 8; i++) {
            float sz = zv[i] / (1.f + __expf(-zv[i]));
            out[i] = xc[i] * (gate + dd[i]) * sz;
        }

        size_t yo = ((size_t)b * TD + t) * DI + c0;
        *(uint4*)(g_y + yo) = make_uint4(
            pack_h2(out[0], out[1]), pack_h2(out[2], out[3]),
            pack_h2(out[4], out[5]), pack_h2(out[6], out[7]));

        #pragma unroll
        for (int i = 0; i < 8; i++) { w0[i] = w1[i]; w1[i] = w2[i]; w2[i] = cur[i]; }
    }
}

// ---------------------------------------------------------------------------
extern "C" void kernel_launch(void* const* d_in, const int* in_sizes, int n_in,
                              void* d_out, int out_size)
{
    const float* x       = (const float*)d_in[0];
    const float* norm_w  = (const float*)d_in[1];
    const float* norm_b  = (const float*)d_in[2];
    const float* in_w    = (const float*)d_in[3];
    const float* in_b    = (const float*)d_in[4];
    const float* conv_w  = (const float*)d_in[5];
    const float* conv_b  = (const float*)d_in[6];
    const float* xproj_w = (const float*)d_in[7];
    const float* Dp      = (const float*)d_in[9];
    const float* out_w   = (const float*)d_in[10];
    const float* out_b   = (const float*)d_in[11];
    float* out = (float*)d_out;

    __half *xn_p, *y_p, *w1_p, *w2_p;
    float *xz_p;
    cudaGetSymbolAddress((void**)&xn_p, g_xn);
    cudaGetSymbolAddress((void**)&xz_p, g_xz);
    cudaGetSymbolAddress((void**)&y_p,  g_y);
    cudaGetSymbolAddress((void**)&w1_p, g_w1);
    cudaGetSymbolAddress((void**)&w2_p, g_w2);

    static int smem_set = 0;
    if (!smem_set) {
        cudaFuncSetAttribute(gemm_hmma_f16,
                             cudaFuncAttributeMaxDynamicSharedMemorySize, GEMM_SMEM);
        smem_set = 1;
    }

    // weight converts (elementwise, tiny)
    {
        int n4a = (2 * DI) * DM / 4;
        wconv_k<<<(n4a + 255) / 256, 256>>>(in_w, w1_p, n4a);
        int n4b = DM * DI / 4;
        wconv_k<<<(n4b + 255) / 256, 256>>>(out_w, w2_p, n4b);
    }
    compute_wbar_k<<<(DI + 255) / 256, 256>>>(xproj_w);
    layernorm_k<<<(int)MROWS, 256>>>(x, norm_w, norm_b);

    // GEMM1: xz = xn @ in_w.T + in_b   (M=16384, N=4096, K=1024)
    gemm_hmma_f16<<<dim3((2 * DI) / G_BN, (int)MROWS / G_BM), 512, GEMM_SMEM>>>(
        xn_p, w1_p, in_b, nullptr, xz_p, 2 * DI, DM);

    // conv + silu + gate + z-gate -> y (fp16)
    fused_mid_k<<<dim3(TD / TT, BD), 256>>>(conv_w, conv_b, Dp);

    // GEMM2: out = y @ out_w.T + out_b + x   (M=16384, N=1024, K=2048)
    gemm_hmma_f16<<<dim3(DM / G_BN, (int)MROWS / G_BM), 512, GEMM_SMEM>>>(
        y_p, w2_p, out_b, x, out, DM, DI);
}

// round 12
// speedup vs baseline: 4.9092x; 1.0336x over previous
#include <cuda_runtime.h>
#include <cuda_fp16.h>
#include <math.h>
#include <stdint.h>

// Problem constants
static constexpr int  BD = 4;
static constexpr int  TD = 4096;
static constexpr int  DM = 1024;           // d_model
static constexpr int  DI = 2048;           // d_inner
static constexpr size_t MROWS = (size_t)BD * TD;   // 16384

// Scratch (fp16 single-plane operands; xz now fp16 too)
__device__ __half g_xn[MROWS * DM];
__device__ __half g_xz[MROWS * 2 * DI];
__device__ __half g_y [MROWS * DI];
__device__ __half g_w1[(size_t)(2 * DI) * DM];
__device__ __half g_w2[(size_t)DM * DI];
__device__ float  g_wbar[DI];

// ===========================================================================
// PTX helpers (sm_80-class — valid at base sm_103 target)
// ===========================================================================
__device__ __forceinline__ uint32_t smem_u32(const void* p) {
    uint32_t a;
    asm("{ .reg .u64 t; cvta.to.shared.u64 t, %1; cvt.u32.u64 %0, t; }"
        : "=r"(a) : "l"(p));
    return a;
}
__device__ __forceinline__ void ldsm_x4(uint32_t* r, uint32_t addr) {
    asm volatile("ldmatrix.sync.aligned.m8n8.x4.shared.b16 {%0,%1,%2,%3}, [%4];"
                 : "=r"(r[0]), "=r"(r[1]), "=r"(r[2]), "=r"(r[3]) : "r"(addr));
}
__device__ __forceinline__ void mma_fp16(float* d, const uint32_t* a,
                                         uint32_t b0, uint32_t b1) {
    asm volatile(
        "mma.sync.aligned.m16n8k16.row.col.f32.f16.f16.f32 "
        "{%0,%1,%2,%3}, {%4,%5,%6,%7}, {%8,%9}, {%0,%1,%2,%3};"
        : "+f"(d[0]), "+f"(d[1]), "+f"(d[2]), "+f"(d[3])
        : "r"(a[0]), "r"(a[1]), "r"(a[2]), "r"(a[3]), "r"(b0), "r"(b1));
}
__device__ __forceinline__ uint32_t pack_h2(float a, float b) {
    __half2 h = __floats2half2_rn(a, b);   // a -> low half
    return *(uint32_t*)&h;
}
// load 8 consecutive halves -> 8 floats
__device__ __forceinline__ void load8h(float* d, const __half* p) {
    uint4 u = *(const uint4*)p;
    float2 f0 = __half22float2(*(__half2*)&u.x);
    float2 f1 = __half22float2(*(__half2*)&u.y);
    float2 f2 = __half22float2(*(__half2*)&u.z);
    float2 f3 = __half22float2(*(__half2*)&u.w);
    d[0]=f0.x; d[1]=f0.y; d[2]=f1.x; d[3]=f1.y;
    d[4]=f2.x; d[5]=f2.y; d[6]=f3.x; d[7]=f3.y;
}
#define CP_ASYNC16(dst, src) \
    asm volatile("cp.async.cg.shared.global [%0], [%1], 16;" \
                 :: "r"(dst), "l"(src) : "memory")
#define CP_COMMIT() asm volatile("cp.async.commit_group;" ::: "memory")
#define CP_WAIT1()  asm volatile("cp.async.wait_group 1;" ::: "memory")
#define CP_WAIT0()  asm volatile("cp.async.wait_group 0;" ::: "memory")

// ===========================================================================
// fp16 HMMA GEMM: C = A @ W^T + bias (+ resid).  Output fp32 or fp16.
// BM=128, BN=256, BK=64; 512 threads (16 warps, 4x4, warp tile 32x64);
// 3-stage cp.async. SMEM rows 144B (128B data + 16B pad) -> conflict-free.
// ===========================================================================
#define G_BM 128
#define G_BN 256
#define G_BK 64
#define ROWB 144
static constexpr int TILE_A  = 128 * ROWB;            // 18432 B
static constexpr int TILE_BB = 256 * ROWB;            // 36864 B
static constexpr int STAGE_B = TILE_A + TILE_BB;      // 55296 B
static constexpr int GEMM_SMEM = 3 * STAGE_B;         // 165888 B

__global__ __launch_bounds__(512, 1)
void gemm_hmma_f16(const __half* __restrict__ Ah,
                   const __half* __restrict__ Wh,
                   const float* __restrict__ bias,
                   const float* __restrict__ resid,   // fp32 or nullptr
                   void* __restrict__ Cout,           // fp32 if resid, else fp16
                   int N, int K, int out_fp16)
{
    extern __shared__ __align__(16) unsigned char dsm[];
    const uint32_t sb = smem_u32(dsm);

    const int tid  = threadIdx.x;
    const int wid  = tid >> 5, lane = tid & 31;
    const int wm   = wid & 3;          // warp m-block (32 rows)
    const int wn   = wid >> 2;         // warp n-block (64 cols)
    const int m0   = blockIdx.y * G_BM;
    const int n0   = blockIdx.x * G_BN;

    const uint32_t frag_off = (uint32_t)((lane & 15) * ROWB + (lane >> 4) * 16);

    float acc[2][8][4];
    #pragma unroll
    for (int i = 0; i < 2; i++)
        #pragma unroll
        for (int j = 0; j < 8; j++)
            #pragma unroll
            for (int q = 0; q < 4; q++) acc[i][j][q] = 0.f;

    auto issue = [&](int it, int stg) {
        const int k0 = it * G_BK;
        const uint32_t st = sb + stg * STAGE_B;
        #pragma unroll
        for (int j = 0; j < 2; j++) {          // A: 1024 16B chunks
            int idx = tid + j * 512;
            int row = idx >> 3, c16 = idx & 7;
            CP_ASYNC16(st + (uint32_t)(row * ROWB + c16 * 16),
                       Ah + (size_t)(m0 + row) * K + k0 + c16 * 8);
        }
        #pragma unroll
        for (int j = 0; j < 4; j++) {          // B: 2048 16B chunks
            int idx = tid + j * 512;
            int row = idx >> 3, c16 = idx & 7;
            CP_ASYNC16(st + TILE_A + (uint32_t)(row * ROWB + c16 * 16),
                       Wh + (size_t)(n0 + row) * K + k0 + c16 * 8);
        }
    };

    const int KC = K / G_BK;
    issue(0, 0); CP_COMMIT();
    issue(1, 1); CP_COMMIT();

    int s_rd = 0, s_wr = 2;
    for (int it = 0; it < KC; it++) {
        if (it + 1 < KC) CP_WAIT1(); else CP_WAIT0();
        __syncthreads();

        if (it + 2 < KC) { issue(it + 2, s_wr); CP_COMMIT(); }

        const uint32_t st = sb + s_rd * STAGE_B;
        #pragma unroll
        for (int kc = 0; kc < 4; kc++) {
            uint32_t a[2][4], b[4][4];
            #pragma unroll
            for (int mi = 0; mi < 2; mi++) {
                uint32_t base = (uint32_t)((wm * 32 + mi * 16) * ROWB + kc * 32) + frag_off;
                ldsm_x4(a[mi], st + base);
            }
            #pragma unroll
            for (int nj = 0; nj < 4; nj++) {
                uint32_t base = (uint32_t)((wn * 64 + nj * 16) * ROWB + kc * 32) + frag_off;
                ldsm_x4(b[nj], st + TILE_A + base);
            }
            #pragma unroll
            for (int mi = 0; mi < 2; mi++)
                #pragma unroll
                for (int nj = 0; nj < 4; nj++)
                    #pragma unroll
                    for (int h = 0; h < 2; h++)
                        mma_fp16(acc[mi][nj * 2 + h], a[mi], b[nj][h], b[nj][h + 2]);
        }
        s_rd = (s_rd + 1 == 3) ? 0 : s_rd + 1;
        s_wr = (s_wr + 1 == 3) ? 0 : s_wr + 1;
    }

    // ---- epilogue ----
    const int lg = lane >> 2;
    const int lq = lane & 3;
    if (out_fp16) {
        __half* C = (__half*)Cout;
        #pragma unroll
        for (int mi = 0; mi < 2; mi++) {
            const int mbase = m0 + wm * 32 + mi * 16 + lg;
            #pragma unroll
            for (int ni = 0; ni < 8; ni++) {
                const int n = n0 + wn * 64 + ni * 8 + lq * 2;
                float2 bv = *(const float2*)(bias + n);
                float* a = acc[mi][ni];
                *(uint32_t*)(C + (size_t)mbase * N + n) =
                    pack_h2(a[0] + bv.x, a[1] + bv.y);
                *(uint32_t*)(C + (size_t)(mbase + 8) * N + n) =
                    pack_h2(a[2] + bv.x, a[3] + bv.y);
            }
        }
    } else {
        float* C = (float*)Cout;
        #pragma unroll
        for (int mi = 0; mi < 2; mi++) {
            const int mbase = m0 + wm * 32 + mi * 16 + lg;
            #pragma unroll
            for (int ni = 0; ni < 8; ni++) {
                const int n = n0 + wn * 64 + ni * 8 + lq * 2;
                float2 bv = *(const float2*)(bias + n);
                float* a = acc[mi][ni];
                float2 o0 = make_float2(a[0] + bv.x, a[1] + bv.y);
                float2 o1 = make_float2(a[2] + bv.x, a[3] + bv.y);
                if (resid) {
                    float2 r0 = *(const float2*)(resid + (size_t)mbase * N + n);
                    float2 r1 = *(const float2*)(resid + (size_t)(mbase + 8) * N + n);
                    o0.x += r0.x; o0.y += r0.y;
                    o1.x += r1.x; o1.y += r1.y;
                }
                *(float2*)(C + (size_t)mbase * N + n)       = o0;
                *(float2*)(C + (size_t)(mbase + 8) * N + n) = o1;
            }
        }
    }
}

// ---------------------------------------------------------------------------
// Weight fp32 -> fp16 convert
// ---------------------------------------------------------------------------
__global__ void wconv_k(const float* __restrict__ w,
                        __half* __restrict__ wh, int n4)
{
    int i = blockIdx.x * blockDim.x + threadIdx.x;
    if (i < n4) {
        float4 v = *(const float4*)(w + (size_t)i * 4);
        *(uint2*)(wh + (size_t)i * 4) =
            make_uint2(pack_h2(v.x, v.y), pack_h2(v.z, v.w));
    }
}

// ---------------------------------------------------------------------------
// wbar[c] = (1/16) * sum_s xproj_w[17+s, c]
// ---------------------------------------------------------------------------
__global__ void compute_wbar_k(const float* __restrict__ xproj_w)
{
    int c = blockIdx.x * blockDim.x + threadIdx.x;
    if (c < DI) {
        float s = 0.f;
        #pragma unroll
        for (int k = 0; k < 16; k++)
            s += xproj_w[(size_t)(17 + k) * DI + c];
        g_wbar[c] = s * (1.f / 16.f);
    }
}

// ---------------------------------------------------------------------------
// LayerNorm -> fp16 plane
// ---------------------------------------------------------------------------
__global__ void layernorm_k(const float* __restrict__ x,
                            const float* __restrict__ w,
                            const float* __restrict__ b)
{
    __shared__ float2 red[256];
    size_t row = blockIdx.x;
    int tid = threadIdx.x;

    const float4* xr = (const float4*)(x + row * DM);
    float4 v = xr[tid];
    float s  = v.x + v.y + v.z + v.w;
    float ss = v.x * v.x + v.y * v.y + v.z * v.z + v.w * v.w;
    red[tid] = make_float2(s, ss);
    __syncthreads();
    #pragma unroll
    for (int off = 128; off >= 1; off >>= 1) {
        if (tid < off) {
            red[tid].x += red[tid + off].x;
            red[tid].y += red[tid + off].y;
        }
        __syncthreads();
    }
    float mu  = red[0].x * (1.f / DM);
    float var = red[0].y * (1.f / DM) - mu * mu;
    float rstd = rsqrtf(var + 1e-5f);

    int c = tid * 4;
    const float4 wv = *(const float4*)(w + c);
    const float4 bv = *(const float4*)(b + c);
    float4 o;
    o.x = (v.x - mu) * rstd * wv.x + bv.x;
    o.y = (v.y - mu) * rstd * wv.y + bv.y;
    o.z = (v.z - mu) * rstd * wv.z + bv.z;
    o.w = (v.w - mu) * rstd * wv.w + bv.w;

    *(uint2*)(g_xn + row * DM + c) =
        make_uint2(pack_h2(o.x, o.y), pack_h2(o.z, o.w));
}

// ---------------------------------------------------------------------------
// Fused mid: conv(4) + SiLU + gate + z-gate -> fp16 plane of y (fp16 xz in)
// ---------------------------------------------------------------------------
#define TT 16

__global__ __launch_bounds__(256)
void fused_mid_k(const float* __restrict__ conv_w,
                 const float* __restrict__ conv_b,
                 const float* __restrict__ Dp)
{
    __shared__ float red[8];
    __shared__ float gate_sh;
    const int b   = blockIdx.y;
    const int t0  = blockIdx.x * TT;
    const int tid = threadIdx.x;
    const int lane = tid & 31, wrp = tid >> 5;
    const int c0 = tid * 8;

    float cw0[8], cw1[8], cw2[8], cw3[8], cb[8], wb[8], dd[8];
    #pragma unroll
    for (int i = 0; i < 8; i++) {
        float4 q = *(const float4*)(conv_w + (size_t)(c0 + i) * 4);
        cw0[i] = q.x; cw1[i] = q.y; cw2[i] = q.z; cw3[i] = q.w;
        cb[i] = conv_b[c0 + i];
        wb[i] = g_wbar[c0 + i];
        dd[i] = Dp[c0 + i];
    }

    float w0[8], w1[8], w2[8];
    #pragma unroll
    for (int j = 0; j < 3; j++) {
        int t = t0 - 3 + j;
        float* dst = (j == 0) ? w0 : (j == 1) ? w1 : w2;
        if (t >= 0) {
            load8h(dst, g_xz + ((size_t)b * TD + t) * (2 * DI) + c0);
        } else {
            #pragma unroll
            for (int i = 0; i < 8; i++) dst[i] = 0.f;
        }
    }

    for (int tt = 0; tt < TT; tt++) {
        const int t = t0 + tt;
        const size_t rb = ((size_t)b * TD + t) * (2 * DI);

        float cur[8];
        load8h(cur, g_xz + rb + c0);

        float xc[8], partial = 0.f;
        #pragma unroll
        for (int i = 0; i < 8; i++) {
            float a = cb[i] + w0[i]*cw0[i] + w1[i]*cw1[i] + w2[i]*cw2[i] + cur[i]*cw3[i];
            float sg = 1.f / (1.f + __expf(-a));
            xc[i] = a * sg;
            partial += xc[i] * wb[i];
        }

        #pragma unroll
        for (int off = 16; off >= 1; off >>= 1)
            partial += __shfl_xor_sync(0xffffffffu, partial, off);
        if (lane == 0) red[wrp] = partial;
        __syncthreads();
        if (tid == 0) {
            float s = 0.f;
            #pragma unroll
            for (int k = 0; k < 8; k++) s += red[k];
            gate_sh = 1.f / (1.f + __expf(-s));
        }
        __syncthreads();
        const float gate = gate_sh;

        float zv[8];
        load8h(zv, g_xz + rb + DI + c0);

        float out[8];
        #pragma unroll
        for (int i = 0; i < 8; i++) {
            float sz = zv[i] / (1.f + __expf(-zv[i]));
            out[i] = xc[i] * (gate + dd[i]) * sz;
        }

        size_t yo = ((size_t)b * TD + t) * DI + c0;
        *(uint4*)(g_y + yo) = make_uint4(
            pack_h2(out[0], out[1]), pack_h2(out[2], out[3]),
            pack_h2(out[4], out[5]), pack_h2(out[6], out[7]));

        #pragma unroll
        for (int i = 0; i < 8; i++) { w0[i] = w1[i]; w1[i] = w2[i]; w2[i] = cur[i]; }
    }
}

// ---------------------------------------------------------------------------
extern "C" void kernel_launch(void* const* d_in, const int* in_sizes, int n_in,
                              void* d_out, int out_size)
{
    const float* x       = (const float*)d_in[0];
    const float* norm_w  = (const float*)d_in[1];
    const float* norm_b  = (const float*)d_in[2];
    const float* in_w    = (const float*)d_in[3];
    const float* in_b    = (const float*)d_in[4];
    const float* conv_w  = (const float*)d_in[5];
    const float* conv_b  = (const float*)d_in[6];
    const float* xproj_w = (const float*)d_in[7];
    const float* Dp      = (const float*)d_in[9];
    const float* out_w   = (const float*)d_in[10];
    const float* out_b   = (const float*)d_in[11];
    float* out = (float*)d_out;

    __half *xn_p, *xz_p, *y_p, *w1_p, *w2_p;
    cudaGetSymbolAddress((void**)&xn_p, g_xn);
    cudaGetSymbolAddress((void**)&xz_p, g_xz);
    cudaGetSymbolAddress((void**)&y_p,  g_y);
    cudaGetSymbolAddress((void**)&w1_p, g_w1);
    cudaGetSymbolAddress((void**)&w2_p, g_w2);

    static int smem_set = 0;
    if (!smem_set) {
        cudaFuncSetAttribute(gemm_hmma_f16,
                             cudaFuncAttributeMaxDynamicSharedMemorySize, GEMM_SMEM);
        smem_set = 1;
    }

    // weight converts (elementwise, tiny)
    {
        int n4a = (2 * DI) * DM / 4;
        wconv_k<<<(n4a + 255) / 256, 256>>>(in_w, w1_p, n4a);
        int n4b = DM * DI / 4;
        wconv_k<<<(n4b + 255) / 256, 256>>>(out_w, w2_p, n4b);
    }
    compute_wbar_k<<<(DI + 255) / 256, 256>>>(xproj_w);
    layernorm_k<<<(int)MROWS, 256>>>(x, norm_w, norm_b);

    // GEMM1: xz = xn @ in_w.T + in_b   (M=16384, N=4096, K=1024) -> fp16
    gemm_hmma_f16<<<dim3((2 * DI) / G_BN, (int)MROWS / G_BM), 512, GEMM_SMEM>>>(
        xn_p, w1_p, in_b, nullptr, xz_p, 2 * DI, DM, 1);

    // conv + silu + gate + z-gate -> y (fp16)
    fused_mid_k<<<dim3(TD / TT, BD), 256>>>(conv_w, conv_b, Dp);

    // GEMM2: out = y @ out_w.T + out_b + x   (M=16384, N=1024, K=2048) -> fp32
    gemm_hmma_f16<<<dim3(DM / G_BN, (int)MROWS / G_BM), 512, GEMM_SMEM>>>(
        y_p, w2_p, out_b, x, out, DM, DI, 0);
}

// round 13
// speedup vs baseline: 4.9623x; 1.0108x over previous
#include <cuda_runtime.h>
#include <cuda_fp16.h>
#include <math.h>
#include <stdint.h>

// Problem constants
static constexpr int  BD = 4;
static constexpr int  TD = 4096;
static constexpr int  DM = 1024;           // d_model
static constexpr int  DI = 2048;           // d_inner
static constexpr size_t MROWS = (size_t)BD * TD;   // 16384

// Scratch (fp16 single-plane operands)
__device__ __half g_xn[MROWS * DM];
__device__ __half g_xz[MROWS * 2 * DI];
__device__ __half g_y [MROWS * DI];
__device__ __half g_w1[(size_t)(2 * DI) * DM];
__device__ __half g_w2[(size_t)DM * DI];
__device__ float  g_wbar[DI];

// ===========================================================================
// PTX helpers (sm_80-class — valid at base sm_103 target)
// ===========================================================================
__device__ __forceinline__ uint32_t smem_u32(const void* p) {
    uint32_t a;
    asm("{ .reg .u64 t; cvta.to.shared.u64 t, %1; cvt.u32.u64 %0, t; }"
        : "=r"(a) : "l"(p));
    return a;
}
__device__ __forceinline__ void ldsm_x4(uint32_t* r, uint32_t addr) {
    asm volatile("ldmatrix.sync.aligned.m8n8.x4.shared.b16 {%0,%1,%2,%3}, [%4];"
                 : "=r"(r[0]), "=r"(r[1]), "=r"(r[2]), "=r"(r[3]) : "r"(addr));
}
__device__ __forceinline__ void mma_fp16(float* d, const uint32_t* a,
                                         uint32_t b0, uint32_t b1) {
    asm volatile(
        "mma.sync.aligned.m16n8k16.row.col.f32.f16.f16.f32 "
        "{%0,%1,%2,%3}, {%4,%5,%6,%7}, {%8,%9}, {%0,%1,%2,%3};"
        : "+f"(d[0]), "+f"(d[1]), "+f"(d[2]), "+f"(d[3])
        : "r"(a[0]), "r"(a[1]), "r"(a[2]), "r"(a[3]), "r"(b0), "r"(b1));
}
__device__ __forceinline__ uint32_t pack_h2(float a, float b) {
    __half2 h = __floats2half2_rn(a, b);   // a -> low half
    return *(uint32_t*)&h;
}
// load 8 consecutive halves -> 8 floats
__device__ __forceinline__ void load8h(float* d, const __half* p) {
    uint4 u = *(const uint4*)p;
    float2 f0 = __half22float2(*(__half2*)&u.x);
    float2 f1 = __half22float2(*(__half2*)&u.y);
    float2 f2 = __half22float2(*(__half2*)&u.z);
    float2 f3 = __half22float2(*(__half2*)&u.w);
    d[0]=f0.x; d[1]=f0.y; d[2]=f1.x; d[3]=f1.y;
    d[4]=f2.x; d[5]=f2.y; d[6]=f3.x; d[7]=f3.y;
}
#define CP_ASYNC16(dst, src) \
    asm volatile("cp.async.cg.shared.global [%0], [%1], 16;" \
                 :: "r"(dst), "l"(src) : "memory")
#define CP_COMMIT() asm volatile("cp.async.commit_group;" ::: "memory")
#define CP_WAIT1()  asm volatile("cp.async.wait_group 1;" ::: "memory")
#define CP_WAIT0()  asm volatile("cp.async.wait_group 0;" ::: "memory")

// ===========================================================================
// fp16 HMMA GEMM, templated on BN (256 for GEMM1, 128 for GEMM2 wave-fit).
// BM=128, BK=64; 512 threads (16 warps, 4x4); 3-stage cp.async.
// SMEM rows 144B (128B data + 16B pad) -> conflict-free ldmatrix.
// K-iteration order identical for both BN -> outputs bit-identical vs BN=256.
// ===========================================================================
#define G_BM 128
#define G_BK 64
#define ROWB 144
static constexpr int TILE_A = 128 * ROWB;             // 18432 B

template <int BN>
__global__ __launch_bounds__(512, 1)
void gemm_hmma_f16(const __half* __restrict__ Ah,
                   const __half* __restrict__ Wh,
                   const float* __restrict__ bias,
                   const float* __restrict__ resid,   // fp32 or nullptr
                   void* __restrict__ Cout,           // fp16 if out_fp16 else fp32
                   int N, int K, int out_fp16)
{
    constexpr int TILE_BBt = BN * ROWB;
    constexpr int STAGE    = TILE_A + TILE_BBt;
    constexpr int NFRAG    = BN / 64;      // B-frags per warp per kc (4 or 2)
    constexpr int WNW      = BN / 4;       // warp n-tile width (64 or 32)

    extern __shared__ __align__(16) unsigned char dsm[];
    const uint32_t sb = smem_u32(dsm);

    const int tid  = threadIdx.x;
    const int wid  = tid >> 5, lane = tid & 31;
    const int wm   = wid & 3;
    const int wn   = wid >> 2;
    const int m0   = blockIdx.y * G_BM;
    const int n0   = blockIdx.x * BN;

    const uint32_t frag_off = (uint32_t)((lane & 15) * ROWB + (lane >> 4) * 16);

    float acc[2][NFRAG * 2][4];
    #pragma unroll
    for (int i = 0; i < 2; i++)
        #pragma unroll
        for (int j = 0; j < NFRAG * 2; j++)
            #pragma unroll
            for (int q = 0; q < 4; q++) acc[i][j][q] = 0.f;

    auto issue = [&](int it, int stg) {
        const int k0 = it * G_BK;
        const uint32_t st = sb + stg * STAGE;
        #pragma unroll
        for (int j = 0; j < 2; j++) {            // A: 1024 16B chunks
            int idx = tid + j * 512;
            int row = idx >> 3, c16 = idx & 7;
            CP_ASYNC16(st + (uint32_t)(row * ROWB + c16 * 16),
                       Ah + (size_t)(m0 + row) * K + k0 + c16 * 8);
        }
        #pragma unroll
        for (int j = 0; j < BN / 64; j++) {      // B: BN*8 16B chunks
            int idx = tid + j * 512;
            int row = idx >> 3, c16 = idx & 7;
            CP_ASYNC16(st + TILE_A + (uint32_t)(row * ROWB + c16 * 16),
                       Wh + (size_t)(n0 + row) * K + k0 + c16 * 8);
        }
    };

    const int KC = K / G_BK;
    issue(0, 0); CP_COMMIT();
    issue(1, 1); CP_COMMIT();

    int s_rd = 0, s_wr = 2;
    for (int it = 0; it < KC; it++) {
        if (it + 1 < KC) CP_WAIT1(); else CP_WAIT0();
        __syncthreads();

        if (it + 2 < KC) { issue(it + 2, s_wr); CP_COMMIT(); }

        const uint32_t st = sb + s_rd * STAGE;
        #pragma unroll
        for (int kc = 0; kc < 4; kc++) {
            uint32_t a[2][4], b[NFRAG][4];
            #pragma unroll
            for (int mi = 0; mi < 2; mi++) {
                uint32_t base = (uint32_t)((wm * 32 + mi * 16) * ROWB + kc * 32) + frag_off;
                ldsm_x4(a[mi], st + base);
            }
            #pragma unroll
            for (int nj = 0; nj < NFRAG; nj++) {
                uint32_t base = (uint32_t)((wn * WNW + nj * 16) * ROWB + kc * 32) + frag_off;
                ldsm_x4(b[nj], st + TILE_A + base);
            }
            #pragma unroll
            for (int mi = 0; mi < 2; mi++)
                #pragma unroll
                for (int nj = 0; nj < NFRAG; nj++)
                    #pragma unroll
                    for (int h = 0; h < 2; h++)
                        mma_fp16(acc[mi][nj * 2 + h], a[mi], b[nj][h], b[nj][h + 2]);
        }
        s_rd = (s_rd + 1 == 3) ? 0 : s_rd + 1;
        s_wr = (s_wr + 1 == 3) ? 0 : s_wr + 1;
    }

    // ---- epilogue ----
    const int lg = lane >> 2;
    const int lq = lane & 3;
    if (out_fp16) {
        __half* C = (__half*)Cout;
        #pragma unroll
        for (int mi = 0; mi < 2; mi++) {
            const int mbase = m0 + wm * 32 + mi * 16 + lg;
            #pragma unroll
            for (int ni = 0; ni < NFRAG * 2; ni++) {
                const int n = n0 + wn * WNW + ni * 8 + lq * 2;
                float2 bv = *(const float2*)(bias + n);
                float* a = acc[mi][ni];
                *(uint32_t*)(C + (size_t)mbase * N + n) =
                    pack_h2(a[0] + bv.x, a[1] + bv.y);
                *(uint32_t*)(C + (size_t)(mbase + 8) * N + n) =
                    pack_h2(a[2] + bv.x, a[3] + bv.y);
            }
        }
    } else {
        float* C = (float*)Cout;
        #pragma unroll
        for (int mi = 0; mi < 2; mi++) {
            const int mbase = m0 + wm * 32 + mi * 16 + lg;
            #pragma unroll
            for (int ni = 0; ni < NFRAG * 2; ni++) {
                const int n = n0 + wn * WNW + ni * 8 + lq * 2;
                float2 bv = *(const float2*)(bias + n);
                float* a = acc[mi][ni];
                float2 o0 = make_float2(a[0] + bv.x, a[1] + bv.y);
                float2 o1 = make_float2(a[2] + bv.x, a[3] + bv.y);
                if (resid) {
                    float2 r0 = *(const float2*)(resid + (size_t)mbase * N + n);
                    float2 r1 = *(const float2*)(resid + (size_t)(mbase + 8) * N + n);
                    o0.x += r0.x; o0.y += r0.y;
                    o1.x += r1.x; o1.y += r1.y;
                }
                *(float2*)(C + (size_t)mbase * N + n)       = o0;
                *(float2*)(C + (size_t)(mbase + 8) * N + n) = o1;
            }
        }
    }
}

static constexpr int SMEM_BN256 = 3 * (TILE_A + 256 * ROWB);  // 165888
static constexpr int SMEM_BN128 = 3 * (TILE_A + 128 * ROWB);  // 110592

// ---------------------------------------------------------------------------
// Weight fp32 -> fp16 convert
// ---------------------------------------------------------------------------
__global__ void wconv_k(const float* __restrict__ w,
                        __half* __restrict__ wh, int n4)
{
    int i = blockIdx.x * blockDim.x + threadIdx.x;
    if (i < n4) {
        float4 v = *(const float4*)(w + (size_t)i * 4);
        *(uint2*)(wh + (size_t)i * 4) =
            make_uint2(pack_h2(v.x, v.y), pack_h2(v.z, v.w));
    }
}

// ---------------------------------------------------------------------------
// wbar[c] = (1/16) * sum_s xproj_w[17+s, c]
// ---------------------------------------------------------------------------
__global__ void compute_wbar_k(const float* __restrict__ xproj_w)
{
    int c = blockIdx.x * blockDim.x + threadIdx.x;
    if (c < DI) {
        float s = 0.f;
        #pragma unroll
        for (int k = 0; k < 16; k++)
            s += xproj_w[(size_t)(17 + k) * DI + c];
        g_wbar[c] = s * (1.f / 16.f);
    }
}

// ---------------------------------------------------------------------------
// LayerNorm -> fp16 plane
// ---------------------------------------------------------------------------
__global__ void layernorm_k(const float* __restrict__ x,
                            const float* __restrict__ w,
                            const float* __restrict__ b)
{
    __shared__ float2 red[256];
    size_t row = blockIdx.x;
    int tid = threadIdx.x;

    const float4* xr = (const float4*)(x + row * DM);
    float4 v = xr[tid];
    float s  = v.x + v.y + v.z + v.w;
    float ss = v.x * v.x + v.y * v.y + v.z * v.z + v.w * v.w;
    red[tid] = make_float2(s, ss);
    __syncthreads();
    #pragma unroll
    for (int off = 128; off >= 1; off >>= 1) {
        if (tid < off) {
            red[tid].x += red[tid + off].x;
            red[tid].y += red[tid + off].y;
        }
        __syncthreads();
    }
    float mu  = red[0].x * (1.f / DM);
    float var = red[0].y * (1.f / DM) - mu * mu;
    float rstd = rsqrtf(var + 1e-5f);

    int c = tid * 4;
    const float4 wv = *(const float4*)(w + c);
    const float4 bv = *(const float4*)(b + c);
    float4 o;
    o.x = (v.x - mu) * rstd * wv.x + bv.x;
    o.y = (v.y - mu) * rstd * wv.y + bv.y;
    o.z = (v.z - mu) * rstd * wv.z + bv.z;
    o.w = (v.w - mu) * rstd * wv.w + bv.w;

    *(uint2*)(g_xn + row * DM + c) =
        make_uint2(pack_h2(o.x, o.y), pack_h2(o.z, o.w));
}

// ---------------------------------------------------------------------------
// Fused mid: conv(4) + SiLU + gate + z-gate -> fp16 plane of y.
// One __syncthreads per timestep via parity double-buffered reduction;
// every thread sums the 8 warp-partials itself (deterministic).
// ---------------------------------------------------------------------------
#define TT 16

__global__ __launch_bounds__(256)
void fused_mid_k(const float* __restrict__ conv_w,
                 const float* __restrict__ conv_b,
                 const float* __restrict__ Dp)
{
    __shared__ float red[2][8];
    const int b   = blockIdx.y;
    const int t0  = blockIdx.x * TT;
    const int tid = threadIdx.x;
    const int lane = tid & 31, wrp = tid >> 5;
    const int c0 = tid * 8;

    float cw0[8], cw1[8], cw2[8], cw3[8], cb[8], wb[8], dd[8];
    #pragma unroll
    for (int i = 0; i < 8; i++) {
        float4 q = *(const float4*)(conv_w + (size_t)(c0 + i) * 4);
        cw0[i] = q.x; cw1[i] = q.y; cw2[i] = q.z; cw3[i] = q.w;
        cb[i] = conv_b[c0 + i];
        wb[i] = g_wbar[c0 + i];
        dd[i] = Dp[c0 + i];
    }

    float w0[8], w1[8], w2[8];
    #pragma unroll
    for (int j = 0; j < 3; j++) {
        int t = t0 - 3 + j;
        float* dst = (j == 0) ? w0 : (j == 1) ? w1 : w2;
        if (t >= 0) {
            load8h(dst, g_xz + ((size_t)b * TD + t) * (2 * DI) + c0);
        } else {
            #pragma unroll
            for (int i = 0; i < 8; i++) dst[i] = 0.f;
        }
    }

    for (int tt = 0; tt < TT; tt++) {
        const int t = t0 + tt;
        const int par = tt & 1;
        const size_t rb = ((size_t)b * TD + t) * (2 * DI);

        float cur[8];
        load8h(cur, g_xz + rb + c0);

        float xc[8], partial = 0.f;
        #pragma unroll
        for (int i = 0; i < 8; i++) {
            float a = cb[i] + w0[i]*cw0[i] + w1[i]*cw1[i] + w2[i]*cw2[i] + cur[i]*cw3[i];
            float sg = 1.f / (1.f + __expf(-a));
            xc[i] = a * sg;
            partial += xc[i] * wb[i];
        }

        #pragma unroll
        for (int off = 16; off >= 1; off >>= 1)
            partial += __shfl_xor_sync(0xffffffffu, partial, off);
        if (lane == 0) red[par][wrp] = partial;
        __syncthreads();
        float ssum = 0.f;
        #pragma unroll
        for (int k = 0; k < 8; k++) ssum += red[par][k];
        const float gate = 1.f / (1.f + __expf(-ssum));

        float zv[8];
        load8h(zv, g_xz + rb + DI + c0);

        float out[8];
        #pragma unroll
        for (int i = 0; i < 8; i++) {
            float sz = zv[i] / (1.f + __expf(-zv[i]));
            out[i] = xc[i] * (gate + dd[i]) * sz;
        }

        size_t yo = ((size_t)b * TD + t) * DI + c0;
        *(uint4*)(g_y + yo) = make_uint4(
            pack_h2(out[0], out[1]), pack_h2(out[2], out[3]),
            pack_h2(out[4], out[5]), pack_h2(out[6], out[7]));

        #pragma unroll
        for (int i = 0; i < 8; i++) { w0[i] = w1[i]; w1[i] = w2[i]; w2[i] = cur[i]; }
    }
}

// ---------------------------------------------------------------------------
extern "C" void kernel_launch(void* const* d_in, const int* in_sizes, int n_in,
                              void* d_out, int out_size)
{
    const float* x       = (const float*)d_in[0];
    const float* norm_w  = (const float*)d_in[1];
    const float* norm_b  = (const float*)d_in[2];
    const float* in_w    = (const float*)d_in[3];
    const float* in_b    = (const float*)d_in[4];
    const float* conv_w  = (const float*)d_in[5];
    const float* conv_b  = (const float*)d_in[6];
    const float* xproj_w = (const float*)d_in[7];
    const float* Dp      = (const float*)d_in[9];
    const float* out_w   = (const float*)d_in[10];
    const float* out_b   = (const float*)d_in[11];
    float* out = (float*)d_out;

    __half *xn_p, *xz_p, *y_p, *w1_p, *w2_p;
    cudaGetSymbolAddress((void**)&xn_p, g_xn);
    cudaGetSymbolAddress((void**)&xz_p, g_xz);
    cudaGetSymbolAddress((void**)&y_p,  g_y);
    cudaGetSymbolAddress((void**)&w1_p, g_w1);
    cudaGetSymbolAddress((void**)&w2_p, g_w2);

    static int smem_set = 0;
    if (!smem_set) {
        cudaFuncSetAttribute(gemm_hmma_f16<256>,
                             cudaFuncAttributeMaxDynamicSharedMemorySize, SMEM_BN256);
        cudaFuncSetAttribute(gemm_hmma_f16<128>,
                             cudaFuncAttributeMaxDynamicSharedMemorySize, SMEM_BN128);
        smem_set = 1;
    }

    // weight converts (elementwise, tiny)
    {
        int n4a = (2 * DI) * DM / 4;
        wconv_k<<<(n4a + 255) / 256, 256>>>(in_w, w1_p, n4a);
        int n4b = DM * DI / 4;
        wconv_k<<<(n4b + 255) / 256, 256>>>(out_w, w2_p, n4b);
    }
    compute_wbar_k<<<(DI + 255) / 256, 256>>>(xproj_w);
    layernorm_k<<<(int)MROWS, 256>>>(x, norm_w, norm_b);

    // GEMM1: xz = xn @ in_w.T + in_b   (M=16384, N=4096, K=1024) -> fp16
    gemm_hmma_f16<256><<<dim3((2 * DI) / 256, (int)MROWS / G_BM), 512, SMEM_BN256>>>(
        xn_p, w1_p, in_b, nullptr, xz_p, 2 * DI, DM, 1);

    // conv + silu + gate + z-gate -> y (fp16)
    fused_mid_k<<<dim3(TD / TT, BD), 256>>>(conv_w, conv_b, Dp);

    // GEMM2: out = y @ out_w.T + out_b + x  (M=16384, N=1024, K=2048) -> fp32
    // BN=128: 1024 CTAs = 6.92 waves (vs 3.46 @BN=256) -> kills 13.5% tail
    gemm_hmma_f16<128><<<dim3(DM / 128, (int)MROWS / G_BM), 512, SMEM_BN128>>>(
        y_p, w2_p, out_b, x, out, DM, DI, 0);
}